// round 12
// baseline (speedup 1.0000x reference)
#include <cuda_runtime.h>
#include <cuda_bf16.h>

#define BB 4
#define CC 256
#define SS 4096
#define HH 4
#define DD 64
#define NROW (BB*SS)   // 16384

// scratch (allocation-free: __device__ globals)
__device__ float g_xt[NROW*CC];
__device__ float g_O[NROW*CC];     // attn out merged heads, tf32-rounded
__device__ float g_av[NROW*CC];
__device__ float g_avn[NROW*CC];   // ln2 out, tf32-rounded
__device__ float g_ff[NROW*CC];    // gelu(ff1), tf32-rounded
__device__ __nv_bfloat16 g_Qh[NROW*CC];
__device__ __nv_bfloat16 g_Kh[NROW*CC];
__device__ __nv_bfloat16 g_Vh[NROW*CC];
__device__ float g_woT[CC*CC];
__device__ float g_w1T[CC*CC];
__device__ float g_w2T[CC*CC];

// ---------------- helpers ----------------
__device__ __forceinline__ unsigned smaddr(const void* p) {
    return (unsigned)__cvta_generic_to_shared(p);
}
__device__ __forceinline__ void ldsm4(unsigned &r0,unsigned &r1,unsigned &r2,unsigned &r3, unsigned a){
    asm volatile("ldmatrix.sync.aligned.m8n8.x4.shared.b16 {%0,%1,%2,%3}, [%4];"
        :"=r"(r0),"=r"(r1),"=r"(r2),"=r"(r3):"r"(a));
}
__device__ __forceinline__ void ldsm4t(unsigned &r0,unsigned &r1,unsigned &r2,unsigned &r3, unsigned a){
    asm volatile("ldmatrix.sync.aligned.m8n8.x4.trans.shared.b16 {%0,%1,%2,%3}, [%4];"
        :"=r"(r0),"=r"(r1),"=r"(r2),"=r"(r3):"r"(a));
}
__device__ __forceinline__ void mma16816(float c[4], const unsigned a[4], const unsigned b[2]){
    asm volatile("mma.sync.aligned.m16n8k16.row.col.f32.bf16.bf16.f32 "
        "{%0,%1,%2,%3},{%4,%5,%6,%7},{%8,%9},{%0,%1,%2,%3};"
        :"+f"(c[0]),"+f"(c[1]),"+f"(c[2]),"+f"(c[3])
        :"r"(a[0]),"r"(a[1]),"r"(a[2]),"r"(a[3]),"r"(b[0]),"r"(b[1]));
}
__device__ __forceinline__ void mma1688_tf32(float c[4], const unsigned a[4], const unsigned b[2]){
    asm volatile("mma.sync.aligned.m16n8k8.row.col.f32.tf32.tf32.f32 "
        "{%0,%1,%2,%3},{%4,%5,%6,%7},{%8,%9},{%0,%1,%2,%3};"
        :"+f"(c[0]),"+f"(c[1]),"+f"(c[2]),"+f"(c[3])
        :"r"(a[0]),"r"(a[1]),"r"(a[2]),"r"(a[3]),"r"(b[0]),"r"(b[1]));
}
__device__ __forceinline__ unsigned packbf(float a, float b){
    __nv_bfloat162 h = __floats2bfloat162_rn(a, b);
    return *(unsigned*)&h;
}
__device__ __forceinline__ float f2tf(float f){
    unsigned u;
    asm("cvt.rna.tf32.f32 %0, %1;" : "=r"(u) : "f"(f));
    return __uint_as_float(u);
}
__device__ __forceinline__ float ex2f(float x){
    float r; asm("ex2.approx.f32 %0, %1;" : "=f"(r) : "f"(x)); return r;
}
__device__ __forceinline__ void cpa16(unsigned s, const void* g){
    asm volatile("cp.async.cg.shared.global [%0], [%1], 16;" :: "r"(s), "l"(g));
}
__device__ __forceinline__ void cpa_commit(){ asm volatile("cp.async.commit_group;"); }
template<int N> __device__ __forceinline__ void cpa_wait(){ asm volatile("cp.async.wait_group %0;" :: "n"(N)); }

// ---------------- K0b: round big weights to tf32 ----------------
__global__ void __launch_bounds__(256) k_wconv(const float* __restrict__ wo,
                                               const float* __restrict__ w1,
                                               const float* __restrict__ w2)
{
    int i = blockIdx.x*256 + threadIdx.x;
    g_woT[i] = f2tf(wo[i]);
    g_w1T[i] = f2tf(w1[i]);
    g_w2T[i] = f2tf(w2[i]);
}

// ---------------- K1: transpose + LN1 + QKV ----------------
#define LN1_SMEM ((256*33 + 3*4096 + 64) * 4)
__global__ void __launch_bounds__(256) k_ln1_qkv(
    const float* __restrict__ x,
    const float* __restrict__ g1, const float* __restrict__ b1,
    const float* __restrict__ wq, const float* __restrict__ bq,
    const float* __restrict__ wk, const float* __restrict__ bk,
    const float* __restrict__ wv, const float* __restrict__ bv)
{
    extern __shared__ float lsm[];
    float* tile = lsm;               // [256][33]
    float* wsq  = lsm + 256*33;      // [64][64]
    float* wsk  = wsq + 4096;
    float* wsv  = wsk + 4096;
    float* mu_s = wsv + 4096;        // [32]
    float* rs_s = mu_s + 32;         // [32]

    int t  = threadIdx.x;
    int s0 = blockIdx.x*32, b = blockIdx.y;
    int tx = t & 31, ty = t >> 5;

    for (int c = ty; c < 256; c += 8)
        tile[c*33 + tx] = x[((size_t)(b*CC) + c)*SS + s0 + tx];
    for (int i = t; i < 1024; i += 256) {
        ((float4*)wsq)[i] = ((const float4*)wq)[i];
        ((float4*)wsk)[i] = ((const float4*)wk)[i];
        ((float4*)wsv)[i] = ((const float4*)wv)[i];
    }
    __syncthreads();

    #pragma unroll 4
    for (int i = 0; i < 32; i++)
        g_xt[((size_t)(b*SS) + s0 + i)*CC + t] = tile[t*33 + i];

    {
        int si = t >> 3, g = t & 7;
        float su = 0.f, sq = 0.f;
        #pragma unroll 8
        for (int c = g*32; c < g*32 + 32; c++) {
            float v = tile[c*33 + si];
            su += v; sq += v*v;
        }
        #pragma unroll
        for (int o = 1; o < 8; o <<= 1) {
            su += __shfl_xor_sync(0xffffffffu, su, o);
            sq += __shfl_xor_sync(0xffffffffu, sq, o);
        }
        if (g == 0) {
            float mu = su * (1.0f/256.0f);
            float var = sq * (1.0f/256.0f) - mu*mu;
            mu_s[si] = mu;
            rs_s[si] = rsqrtf(var + 1e-5f);
        }
    }
    __syncthreads();

    for (int c = ty; c < 256; c += 8) {
        float gg = g1[c], bb = b1[c];
        float v = tile[c*33 + tx];
        tile[c*33 + tx] = (v - mu_s[tx]) * rs_s[tx] * gg + bb;
    }
    __syncthreads();

    int h = t >> 6, dd = t & 63;
    float bqv = bq[dd], bkv = bk[dd], bvv = bv[dd];
    const float* xb = tile + (h*64)*33;
    for (int sb = 0; sb < 32; sb += 8) {
        float aq[8], ak[8], av[8];
        #pragma unroll
        for (int u = 0; u < 8; u++) { aq[u]=bqv; ak[u]=bkv; av[u]=bvv; }
        #pragma unroll 4
        for (int j = 0; j < 64; j++) {
            float wqv = wsq[j*64+dd], wkv = wsk[j*64+dd], wvv2 = wsv[j*64+dd];
            const float* xr = xb + j*33 + sb;
            #pragma unroll
            for (int u = 0; u < 8; u++) {
                float xv = xr[u];
                aq[u] = fmaf(xv, wqv, aq[u]);
                ak[u] = fmaf(xv, wkv, ak[u]);
                av[u] = fmaf(xv, wvv2, av[u]);
            }
        }
        #pragma unroll
        for (int u = 0; u < 8; u++) {
            size_t o = (((size_t)(b*HH + h))*SS + s0 + sb + u)*DD + dd;
            g_Qh[o] = __float2bfloat16(aq[u] * 0.1803368801f);  // 0.125*log2(e)
            g_Kh[o] = __float2bfloat16(ak[u]);
            g_Vh[o] = __float2bfloat16(av[u]);
        }
    }
}

// ---------------- K2: flash attention, interleaved S/exp/PV per chunk ----------------
#define KST 72
#define KVBUF (2*64*KST)
#define ATT_SMEM ((128*KST + 3*KVBUF) * 2)
__global__ void __launch_bounds__(256) k_attn()
{
    extern __shared__ __nv_bfloat16 sm[];
    __nv_bfloat16* Qs = sm;
    __nv_bfloat16* KV = sm + 128*KST;

    int blk = blockIdx.x;
    int bh  = blk >> 5;
    int qt  = blk & 31;
    const __nv_bfloat16* Qp = g_Qh + (size_t)bh * SS * DD;
    const __nv_bfloat16* Kp = g_Kh + (size_t)bh * SS * DD;
    const __nv_bfloat16* Vp = g_Vh + (size_t)bh * SS * DD;
    int t = threadIdx.x, w = t >> 5, lane = t & 31;

    {
        const float4* Qg = (const float4*)(Qp + (size_t)qt*128*DD);
        #pragma unroll
        for (int i = t; i < 1024; i += 256) {
            int r = i >> 3, c = i & 7;
            *(float4*)(Qs + r*KST + c*8) = Qg[i];
        }
    }

    #pragma unroll
    for (int pt = 0; pt < 2; pt++) {
        __nv_bfloat16* Kb = KV + pt*KVBUF;
        __nv_bfloat16* Vb = Kb + 64*KST;
        const __nv_bfloat16* Kg = Kp + (size_t)pt*64*DD;
        const __nv_bfloat16* Vg = Vp + (size_t)pt*64*DD;
        #pragma unroll
        for (int i = t; i < 512; i += 256) {
            int r = i >> 3, c = i & 7;
            cpa16(smaddr(Kb + r*KST + c*8), Kg + r*DD + c*8);
            cpa16(smaddr(Vb + r*KST + c*8), Vg + r*DD + c*8);
        }
        cpa_commit();
    }
    __syncthreads();

    unsigned qf[4][4];
    {
        int row  = w*16 + (lane & 15);
        int colb = (lane >> 4) * 8;
        #pragma unroll
        for (int c = 0; c < 4; c++) {
            unsigned a = smaddr(Qs + row*KST + c*16 + colb);
            ldsm4(qf[c][0], qf[c][1], qf[c][2], qf[c][3], a);
        }
    }

    float o[8][4];
    #pragma unroll
    for (int j = 0; j < 8; j++) { o[j][0]=0.f;o[j][1]=0.f;o[j][2]=0.f;o[j][3]=0.f; }
    float l0 = 0.f, l1 = 0.f;

    int buf = 0;
    for (int kt = 0; kt < 64; kt++) {
        if (kt < 63) cpa_wait<1>(); else cpa_wait<0>();
        __syncthreads();

        if (kt + 2 < 64) {
            int nb = buf + 2; if (nb >= 3) nb -= 3;
            __nv_bfloat16* Kb = KV + nb*KVBUF;
            __nv_bfloat16* Vb = Kb + 64*KST;
            const __nv_bfloat16* Kg = Kp + (size_t)(kt+2)*64*DD;
            const __nv_bfloat16* Vg = Vp + (size_t)(kt+2)*64*DD;
            #pragma unroll
            for (int i = t; i < 512; i += 256) {
                int r = i >> 3, c = i & 7;
                cpa16(smaddr(Kb + r*KST + c*8), Kg + r*DD + c*8);
                cpa16(smaddr(Vb + r*KST + c*8), Vg + r*DD + c*8);
            }
        }
        cpa_commit();

        const __nv_bfloat16* Ks = KV + buf*KVBUF;
        const __nv_bfloat16* Vs = Ks + 64*KST;

        // interleaved: per key-chunk c2, compute S pair -> exp -> PV for that chunk
        #pragma unroll
        for (int c2 = 0; c2 < 4; c2++) {
            float sA[4] = {0.f,0.f,0.f,0.f};
            float sB[4] = {0.f,0.f,0.f,0.f};
            #pragma unroll
            for (int c = 0; c < 4; c++) {
                unsigned kb[4];
                int krow = (2*c2 + ((lane>>4)&1))*8 + (lane&7);
                int kcol = c*16 + ((lane>>3)&1)*8;
                ldsm4(kb[0], kb[1], kb[2], kb[3], smaddr(Ks + krow*KST + kcol));
                mma16816(sA, qf[c], kb);
                mma16816(sB, qf[c], kb+2);
            }
            float a0 = ex2f(sA[0]), a1 = ex2f(sA[1]), a2 = ex2f(sA[2]), a3 = ex2f(sA[3]);
            float b0 = ex2f(sB[0]), b1v = ex2f(sB[1]), b2v = ex2f(sB[2]), b3 = ex2f(sB[3]);
            l0 += a0 + a1 + b0 + b1v;
            l1 += a2 + a3 + b2v + b3;
            unsigned pc[4];
            pc[0] = packbf(a0, a1);
            pc[1] = packbf(a2, a3);
            pc[2] = packbf(b0, b1v);
            pc[3] = packbf(b2v, b3);

            #pragma unroll
            for (int j2 = 0; j2 < 8; j2 += 2) {
                unsigned vb[4];
                int vrow = c2*16 + (lane&15);
                int vcol = (j2 + ((lane>>4)&1))*8;
                ldsm4t(vb[0], vb[1], vb[2], vb[3], smaddr(Vs + vrow*KST + vcol));
                mma16816(o[j2],   pc, vb);
                mma16816(o[j2+1], pc, vb+2);
            }
        }
        buf++; if (buf >= 3) buf = 0;
    }

    l0 += __shfl_xor_sync(0xffffffffu, l0, 1);
    l0 += __shfl_xor_sync(0xffffffffu, l0, 2);
    l1 += __shfl_xor_sync(0xffffffffu, l1, 1);
    l1 += __shfl_xor_sync(0xffffffffu, l1, 2);

    float inv0 = 1.0f / l0, inv1 = 1.0f / l1;
    int g  = lane >> 2, qq = lane & 3;
    int b  = bh >> 2, h = bh & 3;
    int srow0 = qt*128 + w*16 + g;
    size_t base0 = ((size_t)(b*SS) + srow0)*CC + h*64;
    size_t base1 = ((size_t)(b*SS) + srow0 + 8)*CC + h*64;
    #pragma unroll
    for (int j2 = 0; j2 < 8; j2++) {
        *(float2*)(g_O + base0 + j2*8 + qq*2) = make_float2(f2tf(o[j2][0]*inv0), f2tf(o[j2][1]*inv0));
        *(float2*)(g_O + base1 + j2*8 + qq*2) = make_float2(f2tf(o[j2][2]*inv1), f2tf(o[j2][3]*inv1));
    }
}

// ---------------- MODE0 GEMM (full N, LN2 fused) ----------------
#define KCH2 32
#define A3F 36
#define B3F 264
#define ABUF (64*A3F)
#define BBUF (KCH2*B3F)
#define GEMM_SMEM (3*(ABUF + BBUF)*4)   // 129024 B

__global__ void __launch_bounds__(512) k_gemm0(const float* __restrict__ A,
                                               const float* __restrict__ W,
                                               const float* __restrict__ bias,
                                               const float* __restrict__ gamma,
                                               const float* __restrict__ beta)
{
    extern __shared__ char smraw[];
    float* As3 = (float*)smraw;
    float* Bs3 = As3 + 3*ABUF;
    int t = threadIdx.x, w = t >> 5, lane = t & 31;
    int wm = w >> 2, wn = w & 3;
    int r0 = blockIdx.x * 64;

    #pragma unroll
    for (int pc = 0; pc < 2; pc++) {
        {
            int r = t >> 3, c = t & 7;
            cpa16(smaddr(As3 + pc*ABUF + r*A3F + c*4), A + (size_t)(r0 + r)*CC + pc*KCH2 + c*4);
        }
        #pragma unroll
        for (int u = 0; u < 4; u++) {
            int i = t + u*512;
            int k = i >> 6, c = i & 63;
            cpa16(smaddr(Bs3 + pc*BBUF + k*B3F + c*4), W + (size_t)(pc*KCH2 + k)*CC + c*4);
        }
        cpa_commit();
    }

    float acc[8][4];
    #pragma unroll
    for (int j = 0; j < 8; j++) { acc[j][0]=0.f;acc[j][1]=0.f;acc[j][2]=0.f;acc[j][3]=0.f; }

    int ar = lane >> 2, ac = lane & 3;
    int bk = lane & 3,  bn = lane >> 2;

    int buf = 0;
    for (int ch = 0; ch < 8; ch++) {
        if (ch < 7) cpa_wait<1>(); else cpa_wait<0>();
        __syncthreads();

        if (ch + 2 < 8) {
            int nb = buf + 2; if (nb >= 3) nb -= 3;
            int kc = (ch+2)*KCH2;
            {
                int r = t >> 3, c = t & 7;
                cpa16(smaddr(As3 + nb*ABUF + r*A3F + c*4), A + (size_t)(r0 + r)*CC + kc + c*4);
            }
            #pragma unroll
            for (int u = 0; u < 4; u++) {
                int i = t + u*512;
                int k = i >> 6, c = i & 63;
                cpa16(smaddr(Bs3 + nb*BBUF + k*B3F + c*4), W + (size_t)(kc + k)*CC + c*4);
            }
        }
        cpa_commit();

        const float* As = As3 + buf*ABUF;
        const float* Bs = Bs3 + buf*BBUF;
        #pragma unroll
        for (int k8 = 0; k8 < KCH2; k8 += 8) {
            unsigned af[4];
            const float* ab = As + (wm*16 + ar)*A3F + k8 + ac;
            af[0] = __float_as_uint(ab[0]);
            af[1] = __float_as_uint(ab[8*A3F]);
            af[2] = __float_as_uint(ab[4]);
            af[3] = __float_as_uint(ab[8*A3F + 4]);
            #pragma unroll
            for (int j = 0; j < 8; j++) {
                unsigned bf[2];
                const float* bb = Bs + (k8 + bk)*B3F + wn*64 + j*8 + bn;
                bf[0] = __float_as_uint(bb[0]);
                bf[1] = __float_as_uint(bb[4*B3F]);
                mma1688_tf32(acc[j], af, bf);
            }
        }
        buf++; if (buf >= 3) buf = 0;
    }

    int ml = wm*16 + (lane>>2);
    int rlo = r0 + ml, rhi = rlo + 8;

    #pragma unroll
    for (int j = 0; j < 8; j++) {
        int c = wn*64 + j*8 + (lane&3)*2;
        float2 bz = *(const float2*)(bias + c);
        float2 x0 = *(const float2*)(g_xt + (size_t)rlo*CC + c);
        float2 x1 = *(const float2*)(g_xt + (size_t)rhi*CC + c);
        acc[j][0] += bz.x + x0.x; acc[j][1] += bz.y + x0.y;
        acc[j][2] += bz.x + x1.x; acc[j][3] += bz.y + x1.y;
        *(float2*)(g_av + (size_t)rlo*CC + c) = make_float2(acc[j][0], acc[j][1]);
        *(float2*)(g_av + (size_t)rhi*CC + c) = make_float2(acc[j][2], acc[j][3]);
    }
    float sl = 0.f, ql = 0.f, sh = 0.f, qh = 0.f;
    #pragma unroll
    for (int j = 0; j < 8; j++) {
        sl += acc[j][0] + acc[j][1];
        ql += acc[j][0]*acc[j][0] + acc[j][1]*acc[j][1];
        sh += acc[j][2] + acc[j][3];
        qh += acc[j][2]*acc[j][2] + acc[j][3]*acc[j][3];
    }
    #pragma unroll
    for (int oo = 1; oo < 4; oo <<= 1) {
        sl += __shfl_xor_sync(0xffffffffu, sl, oo);
        ql += __shfl_xor_sync(0xffffffffu, ql, oo);
        sh += __shfl_xor_sync(0xffffffffu, sh, oo);
        qh += __shfl_xor_sync(0xffffffffu, qh, oo);
    }
    __syncthreads();
    float* red = (float*)smraw;
    if ((lane & 3) == 0) {
        red[(wn*64 + ml)*2 + 0] = sl;
        red[(wn*64 + ml)*2 + 1] = ql;
        red[(wn*64 + ml + 8)*2 + 0] = sh;
        red[(wn*64 + ml + 8)*2 + 1] = qh;
    }
    __syncthreads();
    float suL=0.f, qL=0.f, suH=0.f, qH=0.f;
    #pragma unroll
    for (int z = 0; z < 4; z++) {
        suL += red[(z*64+ml)*2+0];   qL += red[(z*64+ml)*2+1];
        suH += red[(z*64+ml+8)*2+0]; qH += red[(z*64+ml+8)*2+1];
    }
    float muL = suL*(1.0f/256.0f), vaL = qL*(1.0f/256.0f) - muL*muL;
    float muH = suH*(1.0f/256.0f), vaH = qH*(1.0f/256.0f) - muH*muH;
    float rsL = rsqrtf(vaL + 1e-5f), rsH = rsqrtf(vaH + 1e-5f);
    #pragma unroll
    for (int j = 0; j < 8; j++) {
        int c = wn*64 + j*8 + (lane&3)*2;
        float2 gz = *(const float2*)(gamma + c);
        float2 bz = *(const float2*)(beta + c);
        float n0 = (acc[j][0]-muL)*rsL*gz.x + bz.x;
        float n1 = (acc[j][1]-muL)*rsL*gz.y + bz.y;
        float n2 = (acc[j][2]-muH)*rsH*gz.x + bz.x;
        float n3 = (acc[j][3]-muH)*rsH*gz.y + bz.y;
        *(float2*)(g_avn + (size_t)rlo*CC + c) = make_float2(f2tf(n0), f2tf(n1));
        *(float2*)(g_avn + (size_t)rhi*CC + c) = make_float2(f2tf(n2), f2tf(n3));
    }
}

// ---------------- split-N GEMM: 64x128 tiles, 256 thr, grid (256,2) ----------------
// MODE 1: +bias, gelu -> g_ff(tf32);  MODE 2: +bias +g_av residual -> out transposed
#define N3F 132
#define ABUF2 (64*A3F)
#define BBUF2 (KCH2*N3F)
#define GEMMN_SMEM (3*(ABUF2 + BBUF2)*4)   // 78336 B

template<int MODE>
__global__ void __launch_bounds__(256) k_gemmN(const float* __restrict__ A,
                                               const float* __restrict__ W,
                                               const float* __restrict__ bias,
                                               float* __restrict__ outp)
{
    extern __shared__ char smraw[];
    float* As3 = (float*)smraw;              // 3 x [64][A3F]
    float* Bs3 = As3 + 3*ABUF2;              // 3 x [KCH2][N3F]
    int t = threadIdx.x, w = t >> 5, lane = t & 31;
    int wm = w >> 1, wn = w & 1;
    int r0 = blockIdx.x * 64;
    int n0 = blockIdx.y * 128;

    #pragma unroll
    for (int pc = 0; pc < 2; pc++) {
        #pragma unroll
        for (int u = 0; u < 2; u++) {
            int i = t + u*256;
            int r = i >> 3, c = i & 7;
            cpa16(smaddr(As3 + pc*ABUF2 + r*A3F + c*4), A + (size_t)(r0 + r)*CC + pc*KCH2 + c*4);
        }
        #pragma unroll
        for (int u = 0; u < 4; u++) {
            int i = t + u*256;
            int k = i >> 5, c = i & 31;
            cpa16(smaddr(Bs3 + pc*BBUF2 + k*N3F + c*4), W + (size_t)(pc*KCH2 + k)*CC + n0 + c*4);
        }
        cpa_commit();
    }

    float acc[8][4];
    #pragma unroll
    for (int j = 0; j < 8; j++) { acc[j][0]=0.f;acc[j][1]=0.f;acc[j][2]=0.f;acc[j][3]=0.f; }

    int ar = lane >> 2, ac = lane & 3;
    int bk = lane & 3,  bn = lane >> 2;

    int buf = 0;
    for (int ch = 0; ch < 8; ch++) {
        if (ch < 7) cpa_wait<1>(); else cpa_wait<0>();
        __syncthreads();

        if (ch + 2 < 8) {
            int nb = buf + 2; if (nb >= 3) nb -= 3;
            int kc = (ch+2)*KCH2;
            #pragma unroll
            for (int u = 0; u < 2; u++) {
                int i = t + u*256;
                int r = i >> 3, c = i & 7;
                cpa16(smaddr(As3 + nb*ABUF2 + r*A3F + c*4), A + (size_t)(r0 + r)*CC + kc + c*4);
            }
            #pragma unroll
            for (int u = 0; u < 4; u++) {
                int i = t + u*256;
                int k = i >> 5, c = i & 31;
                cpa16(smaddr(Bs3 + nb*BBUF2 + k*N3F + c*4), W + (size_t)(kc + k)*CC + n0 + c*4);
            }
        }
        cpa_commit();

        const float* As = As3 + buf*ABUF2;
        const float* Bs = Bs3 + buf*BBUF2;
        #pragma unroll
        for (int k8 = 0; k8 < KCH2; k8 += 8) {
            unsigned af[4];
            const float* ab = As + (wm*16 + ar)*A3F + k8 + ac;
            af[0] = __float_as_uint(ab[0]);
            af[1] = __float_as_uint(ab[8*A3F]);
            af[2] = __float_as_uint(ab[4]);
            af[3] = __float_as_uint(ab[8*A3F + 4]);
            #pragma unroll
            for (int j = 0; j < 8; j++) {
                unsigned bf[2];
                const float* bb = Bs + (k8 + bk)*N3F + wn*64 + j*8 + bn;
                bf[0] = __float_as_uint(bb[0]);
                bf[1] = __float_as_uint(bb[4*N3F]);
                mma1688_tf32(acc[j], af, bf);
            }
        }
        buf++; if (buf >= 3) buf = 0;
    }

    int ml = wm*16 + (lane>>2);
    int rlo = r0 + ml, rhi = rlo + 8;

    if (MODE == 1) {
        #pragma unroll
        for (int j = 0; j < 8; j++) {
            int c = n0 + wn*64 + j*8 + (lane&3)*2;
            float2 bz = *(const float2*)(bias + c);
            float f0 = acc[j][0]+bz.x, f1 = acc[j][1]+bz.y;
            float f2 = acc[j][2]+bz.x, f3 = acc[j][3]+bz.y;
            float g0 = 0.5f*f0*(1.0f+erff(f0*0.70710678118654752f));
            float g1 = 0.5f*f1*(1.0f+erff(f1*0.70710678118654752f));
            float g2 = 0.5f*f2*(1.0f+erff(f2*0.70710678118654752f));
            float g3 = 0.5f*f3*(1.0f+erff(f3*0.70710678118654752f));
            *(float2*)(g_ff + (size_t)rlo*CC + c) = make_float2(f2tf(g0), f2tf(g1));
            *(float2*)(g_ff + (size_t)rhi*CC + c) = make_float2(f2tf(g2), f2tf(g3));
        }
    } else {
        __syncthreads();
        float* Ts = (float*)smraw;   // [128][65] = 33280 B
        #pragma unroll
        for (int j = 0; j < 8; j++) {
            int cl = wn*64 + j*8 + (lane&3)*2;
            int c = n0 + cl;
            float2 bz = *(const float2*)(bias + c);
            float2 a0 = *(const float2*)(g_av + (size_t)rlo*CC + c);
            float2 a1 = *(const float2*)(g_av + (size_t)rhi*CC + c);
            Ts[(cl+0)*65 + ml]     = acc[j][0]+bz.x+a0.x;
            Ts[(cl+1)*65 + ml]     = acc[j][1]+bz.y+a0.y;
            Ts[(cl+0)*65 + ml + 8] = acc[j][2]+bz.x+a1.x;
            Ts[(cl+1)*65 + ml + 8] = acc[j][3]+bz.y+a1.y;
        }
        __syncthreads();
        int b  = r0 >> 12;
        int s0 = r0 & 4095;
        for (int i = t; i < 8192; i += 256) {
            int cl = i >> 6, r = i & 63;
            outp[((size_t)(b*CC) + n0 + cl)*SS + s0 + r] = Ts[cl*65 + r];
        }
    }
}

extern "C" void kernel_launch(void* const* d_in, const int* in_sizes, int n_in,
                              void* d_out, int out_size)
{
    const float* x     = (const float*)d_in[0];
    const float* ln1_g = (const float*)d_in[1];
    const float* ln1_b = (const float*)d_in[2];
    const float* wq    = (const float*)d_in[3];
    const float* bq    = (const float*)d_in[4];
    const float* wk    = (const float*)d_in[5];
    const float* bk    = (const float*)d_in[6];
    const float* wv    = (const float*)d_in[7];
    const float* bv    = (const float*)d_in[8];
    const float* wo    = (const float*)d_in[9];
    const float* bo    = (const float*)d_in[10];
    const float* ln2_g = (const float*)d_in[11];
    const float* ln2_b = (const float*)d_in[12];
    const float* w1    = (const float*)d_in[13];
    const float* b1    = (const float*)d_in[14];
    const float* w2    = (const float*)d_in[15];
    const float* b2    = (const float*)d_in[16];
    float* out = (float*)d_out;

    cudaFuncSetAttribute(k_ln1_qkv,  cudaFuncAttributeMaxDynamicSharedMemorySize, LN1_SMEM);
    cudaFuncSetAttribute(k_attn,     cudaFuncAttributeMaxDynamicSharedMemorySize, ATT_SMEM);
    cudaFuncSetAttribute(k_gemm0,    cudaFuncAttributeMaxDynamicSharedMemorySize, GEMM_SMEM);
    cudaFuncSetAttribute(k_gemmN<1>, cudaFuncAttributeMaxDynamicSharedMemorySize, GEMMN_SMEM);
    cudaFuncSetAttribute(k_gemmN<2>, cudaFuncAttributeMaxDynamicSharedMemorySize, GEMMN_SMEM);

    float* woT; cudaGetSymbolAddress((void**)&woT, g_woT);
    float* w1T; cudaGetSymbolAddress((void**)&w1T, g_w1T);
    float* w2T; cudaGetSymbolAddress((void**)&w2T, g_w2T);
    float* O;   cudaGetSymbolAddress((void**)&O,   g_O);
    float* avn; cudaGetSymbolAddress((void**)&avn, g_avn);
    float* ff;  cudaGetSymbolAddress((void**)&ff,  g_ff);

    k_wconv<<<256, 256>>>(wo, w1, w2);
    k_ln1_qkv<<<dim3(SS/32, BB), 256, LN1_SMEM>>>(x, ln1_g, ln1_b, wq, bq, wk, bk, wv, bv);
    k_attn<<<BB*HH*(SS/128), 256, ATT_SMEM>>>();
    k_gemm0<<<NROW/64, 512, GEMM_SMEM>>>(O, woT, bo, ln2_g, ln2_b);
    k_gemmN<1><<<dim3(NROW/64, 2), 256, GEMMN_SMEM>>>(avn, w1T, b1, nullptr);
    k_gemmN<2><<<dim3(NROW/64, 2), 256, GEMMN_SMEM>>>(ff,  w2T, b2, out);
}

// round 13
// speedup vs baseline: 1.0484x; 1.0484x over previous
#include <cuda_runtime.h>
#include <cuda_bf16.h>

#define BB 4
#define CC 256
#define SS 4096
#define HH 4
#define DD 64
#define NROW (BB*SS)   // 16384

// scratch (allocation-free: __device__ globals)
__device__ float g_xt[NROW*CC];
__device__ float g_O[NROW*CC];     // attn out merged heads, tf32-rounded
__device__ float g_av[NROW*CC];
__device__ float g_avn[NROW*CC];   // ln2 out, tf32-rounded
__device__ float g_ff[NROW*CC];    // gelu(ff1), tf32-rounded
__device__ __nv_bfloat16 g_Qh[NROW*CC];
__device__ __nv_bfloat16 g_Kh[NROW*CC];
__device__ __nv_bfloat16 g_Vh[NROW*CC];
__device__ float g_woT[CC*CC];
__device__ float g_w1T[CC*CC];
__device__ float g_w2T[CC*CC];

// ---------------- helpers ----------------
__device__ __forceinline__ unsigned smaddr(const void* p) {
    return (unsigned)__cvta_generic_to_shared(p);
}
__device__ __forceinline__ void ldsm4(unsigned &r0,unsigned &r1,unsigned &r2,unsigned &r3, unsigned a){
    asm volatile("ldmatrix.sync.aligned.m8n8.x4.shared.b16 {%0,%1,%2,%3}, [%4];"
        :"=r"(r0),"=r"(r1),"=r"(r2),"=r"(r3):"r"(a));
}
__device__ __forceinline__ void ldsm4t(unsigned &r0,unsigned &r1,unsigned &r2,unsigned &r3, unsigned a){
    asm volatile("ldmatrix.sync.aligned.m8n8.x4.trans.shared.b16 {%0,%1,%2,%3}, [%4];"
        :"=r"(r0),"=r"(r1),"=r"(r2),"=r"(r3):"r"(a));
}
__device__ __forceinline__ void mma16816(float c[4], const unsigned a[4], const unsigned b[2]){
    asm volatile("mma.sync.aligned.m16n8k16.row.col.f32.bf16.bf16.f32 "
        "{%0,%1,%2,%3},{%4,%5,%6,%7},{%8,%9},{%0,%1,%2,%3};"
        :"+f"(c[0]),"+f"(c[1]),"+f"(c[2]),"+f"(c[3])
        :"r"(a[0]),"r"(a[1]),"r"(a[2]),"r"(a[3]),"r"(b[0]),"r"(b[1]));
}
__device__ __forceinline__ void mma1688_tf32(float c[4], const unsigned a[4], const unsigned b[2]){
    asm volatile("mma.sync.aligned.m16n8k8.row.col.f32.tf32.tf32.f32 "
        "{%0,%1,%2,%3},{%4,%5,%6,%7},{%8,%9},{%0,%1,%2,%3};"
        :"+f"(c[0]),"+f"(c[1]),"+f"(c[2]),"+f"(c[3])
        :"r"(a[0]),"r"(a[1]),"r"(a[2]),"r"(a[3]),"r"(b[0]),"r"(b[1]));
}
__device__ __forceinline__ unsigned packbf(float a, float b){
    __nv_bfloat162 h = __floats2bfloat162_rn(a, b);
    return *(unsigned*)&h;
}
__device__ __forceinline__ float f2tf(float f){
    unsigned u;
    asm("cvt.rna.tf32.f32 %0, %1;" : "=r"(u) : "f"(f));
    return __uint_as_float(u);
}
__device__ __forceinline__ float ex2f(float x){
    float r; asm("ex2.approx.f32 %0, %1;" : "=f"(r) : "f"(x)); return r;
}
__device__ __forceinline__ void cpa16(unsigned s, const void* g){
    asm volatile("cp.async.cg.shared.global [%0], [%1], 16;" :: "r"(s), "l"(g));
}
__device__ __forceinline__ void cpa_commit(){ asm volatile("cp.async.commit_group;"); }
template<int N> __device__ __forceinline__ void cpa_wait(){ asm volatile("cp.async.wait_group %0;" :: "n"(N)); }

// ---------------- K0b: round big weights to tf32 ----------------
__global__ void __launch_bounds__(256) k_wconv(const float* __restrict__ wo,
                                               const float* __restrict__ w1,
                                               const float* __restrict__ w2)
{
    int i = blockIdx.x*256 + threadIdx.x;
    g_woT[i] = f2tf(wo[i]);
    g_w1T[i] = f2tf(w1[i]);
    g_w2T[i] = f2tf(w2[i]);
}

// ---------------- K1: transpose + LN1 + QKV ----------------
#define LN1_SMEM ((256*33 + 3*4096 + 64) * 4)
__global__ void __launch_bounds__(256) k_ln1_qkv(
    const float* __restrict__ x,
    const float* __restrict__ g1, const float* __restrict__ b1,
    const float* __restrict__ wq, const float* __restrict__ bq,
    const float* __restrict__ wk, const float* __restrict__ bk,
    const float* __restrict__ wv, const float* __restrict__ bv)
{
    extern __shared__ float lsm[];
    float* tile = lsm;               // [256][33]
    float* wsq  = lsm + 256*33;      // [64][64]
    float* wsk  = wsq + 4096;
    float* wsv  = wsk + 4096;
    float* mu_s = wsv + 4096;        // [32]
    float* rs_s = mu_s + 32;         // [32]

    int t  = threadIdx.x;
    int s0 = blockIdx.x*32, b = blockIdx.y;
    int tx = t & 31, ty = t >> 5;

    for (int c = ty; c < 256; c += 8)
        tile[c*33 + tx] = x[((size_t)(b*CC) + c)*SS + s0 + tx];
    for (int i = t; i < 1024; i += 256) {
        ((float4*)wsq)[i] = ((const float4*)wq)[i];
        ((float4*)wsk)[i] = ((const float4*)wk)[i];
        ((float4*)wsv)[i] = ((const float4*)wv)[i];
    }
    __syncthreads();

    #pragma unroll 4
    for (int i = 0; i < 32; i++)
        g_xt[((size_t)(b*SS) + s0 + i)*CC + t] = tile[t*33 + i];

    {
        int si = t >> 3, g = t & 7;
        float su = 0.f, sq = 0.f;
        #pragma unroll 8
        for (int c = g*32; c < g*32 + 32; c++) {
            float v = tile[c*33 + si];
            su += v; sq += v*v;
        }
        #pragma unroll
        for (int o = 1; o < 8; o <<= 1) {
            su += __shfl_xor_sync(0xffffffffu, su, o);
            sq += __shfl_xor_sync(0xffffffffu, sq, o);
        }
        if (g == 0) {
            float mu = su * (1.0f/256.0f);
            float var = sq * (1.0f/256.0f) - mu*mu;
            mu_s[si] = mu;
            rs_s[si] = rsqrtf(var + 1e-5f);
        }
    }
    __syncthreads();

    for (int c = ty; c < 256; c += 8) {
        float gg = g1[c], bb = b1[c];
        float v = tile[c*33 + tx];
        tile[c*33 + tx] = (v - mu_s[tx]) * rs_s[tx] * gg + bb;
    }
    __syncthreads();

    int h = t >> 6, dd = t & 63;
    float bqv = bq[dd], bkv = bk[dd], bvv = bv[dd];
    const float* xb = tile + (h*64)*33;
    for (int sb = 0; sb < 32; sb += 8) {
        float aq[8], ak[8], av[8];
        #pragma unroll
        for (int u = 0; u < 8; u++) { aq[u]=bqv; ak[u]=bkv; av[u]=bvv; }
        #pragma unroll 4
        for (int j = 0; j < 64; j++) {
            float wqv = wsq[j*64+dd], wkv = wsk[j*64+dd], wvv2 = wsv[j*64+dd];
            const float* xr = xb + j*33 + sb;
            #pragma unroll
            for (int u = 0; u < 8; u++) {
                float xv = xr[u];
                aq[u] = fmaf(xv, wqv, aq[u]);
                ak[u] = fmaf(xv, wkv, ak[u]);
                av[u] = fmaf(xv, wvv2, av[u]);
            }
        }
        #pragma unroll
        for (int u = 0; u < 8; u++) {
            size_t o = (((size_t)(b*HH + h))*SS + s0 + sb + u)*DD + dd;
            g_Qh[o] = __float2bfloat16(aq[u] * 0.1803368801f);  // 0.125*log2(e)
            g_Kh[o] = __float2bfloat16(ak[u]);
            g_Vh[o] = __float2bfloat16(av[u]);
        }
    }
}

// ---------------- K2: flash attention (R11 structure: all-S then all-PV) ----------------
#define KST 72
#define KVBUF (2*64*KST)
#define ATT_SMEM ((128*KST + 3*KVBUF) * 2)
__global__ void __launch_bounds__(256) k_attn()
{
    extern __shared__ __nv_bfloat16 sm[];
    __nv_bfloat16* Qs = sm;
    __nv_bfloat16* KV = sm + 128*KST;

    int blk = blockIdx.x;
    int bh  = blk >> 5;
    int qt  = blk & 31;
    const __nv_bfloat16* Qp = g_Qh + (size_t)bh * SS * DD;
    const __nv_bfloat16* Kp = g_Kh + (size_t)bh * SS * DD;
    const __nv_bfloat16* Vp = g_Vh + (size_t)bh * SS * DD;
    int t = threadIdx.x, w = t >> 5, lane = t & 31;

    {
        const float4* Qg = (const float4*)(Qp + (size_t)qt*128*DD);
        #pragma unroll
        for (int i = t; i < 1024; i += 256) {
            int r = i >> 3, c = i & 7;
            *(float4*)(Qs + r*KST + c*8) = Qg[i];
        }
    }

    #pragma unroll
    for (int pt = 0; pt < 2; pt++) {
        __nv_bfloat16* Kb = KV + pt*KVBUF;
        __nv_bfloat16* Vb = Kb + 64*KST;
        const __nv_bfloat16* Kg = Kp + (size_t)pt*64*DD;
        const __nv_bfloat16* Vg = Vp + (size_t)pt*64*DD;
        #pragma unroll
        for (int i = t; i < 512; i += 256) {
            int r = i >> 3, c = i & 7;
            cpa16(smaddr(Kb + r*KST + c*8), Kg + r*DD + c*8);
            cpa16(smaddr(Vb + r*KST + c*8), Vg + r*DD + c*8);
        }
        cpa_commit();
    }
    __syncthreads();

    unsigned qf[4][4];
    {
        int row  = w*16 + (lane & 15);
        int colb = (lane >> 4) * 8;
        #pragma unroll
        for (int c = 0; c < 4; c++) {
            unsigned a = smaddr(Qs + row*KST + c*16 + colb);
            ldsm4(qf[c][0], qf[c][1], qf[c][2], qf[c][3], a);
        }
    }

    float o[8][4];
    #pragma unroll
    for (int j = 0; j < 8; j++) { o[j][0]=0.f;o[j][1]=0.f;o[j][2]=0.f;o[j][3]=0.f; }
    float l0 = 0.f, l1 = 0.f;

    int buf = 0;
    for (int kt = 0; kt < 64; kt++) {
        if (kt < 63) cpa_wait<1>(); else cpa_wait<0>();
        __syncthreads();

        if (kt + 2 < 64) {
            int nb = buf + 2; if (nb >= 3) nb -= 3;
            __nv_bfloat16* Kb = KV + nb*KVBUF;
            __nv_bfloat16* Vb = Kb + 64*KST;
            const __nv_bfloat16* Kg = Kp + (size_t)(kt+2)*64*DD;
            const __nv_bfloat16* Vg = Vp + (size_t)(kt+2)*64*DD;
            #pragma unroll
            for (int i = t; i < 512; i += 256) {
                int r = i >> 3, c = i & 7;
                cpa16(smaddr(Kb + r*KST + c*8), Kg + r*DD + c*8);
                cpa16(smaddr(Vb + r*KST + c*8), Vg + r*DD + c*8);
            }
        }
        cpa_commit();

        const __nv_bfloat16* Ks = KV + buf*KVBUF;
        const __nv_bfloat16* Vs = Ks + 64*KST;

        unsigned pa[4][4];
        #pragma unroll
        for (int j = 0; j < 8; j += 2) {
            float sA[4] = {0.f,0.f,0.f,0.f};
            float sB[4] = {0.f,0.f,0.f,0.f};
            #pragma unroll
            for (int c = 0; c < 4; c++) {
                unsigned kb[4];
                int krow = (j + ((lane>>4)&1))*8 + (lane&7);
                int kcol = c*16 + ((lane>>3)&1)*8;
                ldsm4(kb[0], kb[1], kb[2], kb[3], smaddr(Ks + krow*KST + kcol));
                mma16816(sA, qf[c], kb);
                mma16816(sB, qf[c], kb+2);
            }
            float a0 = ex2f(sA[0]), a1 = ex2f(sA[1]), a2 = ex2f(sA[2]), a3 = ex2f(sA[3]);
            float b0 = ex2f(sB[0]), b1v = ex2f(sB[1]), b2v = ex2f(sB[2]), b3 = ex2f(sB[3]);
            l0 += a0 + a1 + b0 + b1v;
            l1 += a2 + a3 + b2v + b3;
            pa[j>>1][0] = packbf(a0, a1);
            pa[j>>1][1] = packbf(a2, a3);
            pa[j>>1][2] = packbf(b0, b1v);
            pa[j>>1][3] = packbf(b2v, b3);
        }

        #pragma unroll
        for (int c2 = 0; c2 < 4; c2++) {
            #pragma unroll
            for (int j2 = 0; j2 < 8; j2 += 2) {
                unsigned vb[4];
                int vrow = c2*16 + (lane&15);
                int vcol = (j2 + ((lane>>4)&1))*8;
                ldsm4t(vb[0], vb[1], vb[2], vb[3], smaddr(Vs + vrow*KST + vcol));
                mma16816(o[j2],   pa[c2], vb);
                mma16816(o[j2+1], pa[c2], vb+2);
            }
        }
        buf++; if (buf >= 3) buf = 0;
    }

    l0 += __shfl_xor_sync(0xffffffffu, l0, 1);
    l0 += __shfl_xor_sync(0xffffffffu, l0, 2);
    l1 += __shfl_xor_sync(0xffffffffu, l1, 1);
    l1 += __shfl_xor_sync(0xffffffffu, l1, 2);

    float inv0 = 1.0f / l0, inv1 = 1.0f / l1;
    int g  = lane >> 2, qq = lane & 3;
    int b  = bh >> 2, h = bh & 3;
    int srow0 = qt*128 + w*16 + g;
    size_t base0 = ((size_t)(b*SS) + srow0)*CC + h*64;
    size_t base1 = ((size_t)(b*SS) + srow0 + 8)*CC + h*64;
    #pragma unroll
    for (int j2 = 0; j2 < 8; j2++) {
        *(float2*)(g_O + base0 + j2*8 + qq*2) = make_float2(f2tf(o[j2][0]*inv0), f2tf(o[j2][1]*inv0));
        *(float2*)(g_O + base1 + j2*8 + qq*2) = make_float2(f2tf(o[j2][2]*inv1), f2tf(o[j2][3]*inv1));
    }
}

// ---------------- tf32 GEMM: 64x256 tiles, 512 thr, 2-stage ring (2 CTAs/SM) ----------------
// MODE 0: +bias +g_xt residual -> g_av, LN2 -> g_avn(tf32)
// MODE 1: +bias, gelu -> g_ff(tf32)
// MODE 2: +bias +g_av residual -> out fp32 transposed [b][c][s]
#define KCH2 32
#define A3F 36
#define B3F 264
#define ABUF (64*A3F)
#define BBUF (KCH2*B3F)
#define GEMM_SMEM (2*(ABUF + BBUF)*4)   // 86016 B -> 2 CTAs/SM

template<int MODE>
__global__ void __launch_bounds__(512) k_gemm(const float* __restrict__ A,
                                              const float* __restrict__ W,
                                              const float* __restrict__ bias,
                                              float* __restrict__ outp,
                                              const float* __restrict__ gamma,
                                              const float* __restrict__ beta)
{
    extern __shared__ char smraw[];
    float* As3 = (float*)smraw;               // 2 x [64][A3F]
    float* Bs3 = As3 + 2*ABUF;                // 2 x [KCH2][B3F]
    int t = threadIdx.x, w = t >> 5, lane = t & 31;
    int wm = w >> 2, wn = w & 3;
    int r0 = blockIdx.x * 64;

    // prologue: chunks 0,1 into bufs 0,1
    #pragma unroll
    for (int pc = 0; pc < 2; pc++) {
        {
            int r = t >> 3, c = t & 7;
            cpa16(smaddr(As3 + pc*ABUF + r*A3F + c*4), A + (size_t)(r0 + r)*CC + pc*KCH2 + c*4);
        }
        #pragma unroll
        for (int u = 0; u < 4; u++) {
            int i = t + u*512;
            int k = i >> 6, c = i & 63;
            cpa16(smaddr(Bs3 + pc*BBUF + k*B3F + c*4), W + (size_t)(pc*KCH2 + k)*CC + c*4);
        }
        cpa_commit();
    }

    float acc[8][4];
    #pragma unroll
    for (int j = 0; j < 8; j++) { acc[j][0]=0.f;acc[j][1]=0.f;acc[j][2]=0.f;acc[j][3]=0.f; }

    int ar = lane >> 2, ac = lane & 3;
    int bk = lane & 3,  bn = lane >> 2;

    int buf = 0;
    for (int ch = 0; ch < 8; ch++) {
        if (ch < 7) cpa_wait<1>(); else cpa_wait<0>();
        __syncthreads();

        const float* As = As3 + buf*ABUF;
        const float* Bs = Bs3 + buf*BBUF;
        #pragma unroll
        for (int k8 = 0; k8 < KCH2; k8 += 8) {
            unsigned af[4];
            const float* ab = As + (wm*16 + ar)*A3F + k8 + ac;
            af[0] = __float_as_uint(ab[0]);
            af[1] = __float_as_uint(ab[8*A3F]);
            af[2] = __float_as_uint(ab[4]);
            af[3] = __float_as_uint(ab[8*A3F + 4]);
            #pragma unroll
            for (int j = 0; j < 8; j++) {
                unsigned bf[2];
                const float* bb = Bs + (k8 + bk)*B3F + wn*64 + j*8 + bn;
                bf[0] = __float_as_uint(bb[0]);
                bf[1] = __float_as_uint(bb[4*B3F]);
                mma1688_tf32(acc[j], af, bf);
            }
        }

        // refill this buffer with chunk ch+2 (after all warps finished reading it)
        if (ch + 2 < 8) {
            __syncthreads();
            int kc = (ch+2)*KCH2;
            {
                int r = t >> 3, c = t & 7;
                cpa16(smaddr(As3 + buf*ABUF + r*A3F + c*4), A + (size_t)(r0 + r)*CC + kc + c*4);
            }
            #pragma unroll
            for (int u = 0; u < 4; u++) {
                int i = t + u*512;
                int k = i >> 6, c = i & 63;
                cpa16(smaddr(Bs3 + buf*BBUF + k*B3F + c*4), W + (size_t)(kc + k)*CC + c*4);
            }
        }
        cpa_commit();
        buf ^= 1;
    }

    int ml = wm*16 + (lane>>2);
    int rlo = r0 + ml, rhi = rlo + 8;

    if (MODE == 0) {
        #pragma unroll
        for (int j = 0; j < 8; j++) {
            int c = wn*64 + j*8 + (lane&3)*2;
            float2 bz = *(const float2*)(bias + c);
            float2 x0 = *(const float2*)(g_xt + (size_t)rlo*CC + c);
            float2 x1 = *(const float2*)(g_xt + (size_t)rhi*CC + c);
            acc[j][0] += bz.x + x0.x; acc[j][1] += bz.y + x0.y;
            acc[j][2] += bz.x + x1.x; acc[j][3] += bz.y + x1.y;
            *(float2*)(g_av + (size_t)rlo*CC + c) = make_float2(acc[j][0], acc[j][1]);
            *(float2*)(g_av + (size_t)rhi*CC + c) = make_float2(acc[j][2], acc[j][3]);
        }
        float sl = 0.f, ql = 0.f, sh = 0.f, qh = 0.f;
        #pragma unroll
        for (int j = 0; j < 8; j++) {
            sl += acc[j][0] + acc[j][1];
            ql += acc[j][0]*acc[j][0] + acc[j][1]*acc[j][1];
            sh += acc[j][2] + acc[j][3];
            qh += acc[j][2]*acc[j][2] + acc[j][3]*acc[j][3];
        }
        #pragma unroll
        for (int oo = 1; oo < 4; oo <<= 1) {
            sl += __shfl_xor_sync(0xffffffffu, sl, oo);
            ql += __shfl_xor_sync(0xffffffffu, ql, oo);
            sh += __shfl_xor_sync(0xffffffffu, sh, oo);
            qh += __shfl_xor_sync(0xffffffffu, qh, oo);
        }
        __syncthreads();
        float* red = (float*)smraw;   // [4 wn][64 rows][2]
        if ((lane & 3) == 0) {
            red[(wn*64 + ml)*2 + 0] = sl;
            red[(wn*64 + ml)*2 + 1] = ql;
            red[(wn*64 + ml + 8)*2 + 0] = sh;
            red[(wn*64 + ml + 8)*2 + 1] = qh;
        }
        __syncthreads();
        float suL=0.f, qL=0.f, suH=0.f, qH=0.f;
        #pragma unroll
        for (int z = 0; z < 4; z++) {
            suL += red[(z*64+ml)*2+0];   qL += red[(z*64+ml)*2+1];
            suH += red[(z*64+ml+8)*2+0]; qH += red[(z*64+ml+8)*2+1];
        }
        float muL = suL*(1.0f/256.0f), vaL = qL*(1.0f/256.0f) - muL*muL;
        float muH = suH*(1.0f/256.0f), vaH = qH*(1.0f/256.0f) - muH*muH;
        float rsL = rsqrtf(vaL + 1e-5f), rsH = rsqrtf(vaH + 1e-5f);
        #pragma unroll
        for (int j = 0; j < 8; j++) {
            int c = wn*64 + j*8 + (lane&3)*2;
            float2 gz = *(const float2*)(gamma + c);
            float2 bz = *(const float2*)(beta + c);
            float n0 = (acc[j][0]-muL)*rsL*gz.x + bz.x;
            float n1 = (acc[j][1]-muL)*rsL*gz.y + bz.y;
            float n2 = (acc[j][2]-muH)*rsH*gz.x + bz.x;
            float n3 = (acc[j][3]-muH)*rsH*gz.y + bz.y;
            *(float2*)(g_avn + (size_t)rlo*CC + c) = make_float2(f2tf(n0), f2tf(n1));
            *(float2*)(g_avn + (size_t)rhi*CC + c) = make_float2(f2tf(n2), f2tf(n3));
        }
    } else if (MODE == 1) {
        #pragma unroll
        for (int j = 0; j < 8; j++) {
            int c = wn*64 + j*8 + (lane&3)*2;
            float2 bz = *(const float2*)(bias + c);
            float f0 = acc[j][0]+bz.x, f1 = acc[j][1]+bz.y;
            float f2 = acc[j][2]+bz.x, f3 = acc[j][3]+bz.y;
            float g0 = 0.5f*f0*(1.0f+erff(f0*0.70710678118654752f));
            float g1 = 0.5f*f1*(1.0f+erff(f1*0.70710678118654752f));
            float g2 = 0.5f*f2*(1.0f+erff(f2*0.70710678118654752f));
            float g3 = 0.5f*f3*(1.0f+erff(f3*0.70710678118654752f));
            *(float2*)(g_ff + (size_t)rlo*CC + c) = make_float2(f2tf(g0), f2tf(g1));
            *(float2*)(g_ff + (size_t)rhi*CC + c) = make_float2(f2tf(g2), f2tf(g3));
        }
    } else {
        __syncthreads();
        float* Ts = (float*)smraw;   // [256][65] = 66560 B <= 86016
        #pragma unroll
        for (int j = 0; j < 8; j++) {
            int c = wn*64 + j*8 + (lane&3)*2;
            float2 bz = *(const float2*)(bias + c);
            float2 a0 = *(const float2*)(g_av + (size_t)rlo*CC + c);
            float2 a1 = *(const float2*)(g_av + (size_t)rhi*CC + c);
            Ts[(c+0)*65 + ml]     = acc[j][0]+bz.x+a0.x;
            Ts[(c+1)*65 + ml]     = acc[j][1]+bz.y+a0.y;
            Ts[(c+0)*65 + ml + 8] = acc[j][2]+bz.x+a1.x;
            Ts[(c+1)*65 + ml + 8] = acc[j][3]+bz.y+a1.y;
        }
        __syncthreads();
        int b  = r0 >> 12;
        int s0 = r0 & 4095;
        for (int i = t; i < 16384; i += 512) {
            int c = i >> 6, r = i & 63;
            outp[((size_t)(b*CC) + c)*SS + s0 + r] = Ts[c*65 + r];
        }
    }
}

extern "C" void kernel_launch(void* const* d_in, const int* in_sizes, int n_in,
                              void* d_out, int out_size)
{
    const float* x     = (const float*)d_in[0];
    const float* ln1_g = (const float*)d_in[1];
    const float* ln1_b = (const float*)d_in[2];
    const float* wq    = (const float*)d_in[3];
    const float* bq    = (const float*)d_in[4];
    const float* wk    = (const float*)d_in[5];
    const float* bk    = (const float*)d_in[6];
    const float* wv    = (const float*)d_in[7];
    const float* bv    = (const float*)d_in[8];
    const float* wo    = (const float*)d_in[9];
    const float* bo    = (const float*)d_in[10];
    const float* ln2_g = (const float*)d_in[11];
    const float* ln2_b = (const float*)d_in[12];
    const float* w1    = (const float*)d_in[13];
    const float* b1    = (const float*)d_in[14];
    const float* w2    = (const float*)d_in[15];
    const float* b2    = (const float*)d_in[16];
    float* out = (float*)d_out;

    cudaFuncSetAttribute(k_ln1_qkv, cudaFuncAttributeMaxDynamicSharedMemorySize, LN1_SMEM);
    cudaFuncSetAttribute(k_attn,    cudaFuncAttributeMaxDynamicSharedMemorySize, ATT_SMEM);
    cudaFuncSetAttribute(k_gemm<0>, cudaFuncAttributeMaxDynamicSharedMemorySize, GEMM_SMEM);
    cudaFuncSetAttribute(k_gemm<1>, cudaFuncAttributeMaxDynamicSharedMemorySize, GEMM_SMEM);
    cudaFuncSetAttribute(k_gemm<2>, cudaFuncAttributeMaxDynamicSharedMemorySize, GEMM_SMEM);

    float* woT; cudaGetSymbolAddress((void**)&woT, g_woT);
    float* w1T; cudaGetSymbolAddress((void**)&w1T, g_w1T);
    float* w2T; cudaGetSymbolAddress((void**)&w2T, g_w2T);
    float* O;   cudaGetSymbolAddress((void**)&O,   g_O);
    float* avn; cudaGetSymbolAddress((void**)&avn, g_avn);
    float* ff;  cudaGetSymbolAddress((void**)&ff,  g_ff);

    k_wconv<<<256, 256>>>(wo, w1, w2);
    k_ln1_qkv<<<dim3(SS/32, BB), 256, LN1_SMEM>>>(x, ln1_g, ln1_b, wq, bq, wk, bk, wv, bv);
    k_attn<<<BB*HH*(SS/128), 256, ATT_SMEM>>>();
    k_gemm<0><<<NROW/64, 512, GEMM_SMEM>>>(O,   woT, bo, nullptr, ln2_g, ln2_b);
    k_gemm<1><<<NROW/64, 512, GEMM_SMEM>>>(avn, w1T, b1, nullptr, nullptr, nullptr);
    k_gemm<2><<<NROW/64, 512, GEMM_SMEM>>>(ff,  w2T, b2, out,     nullptr, nullptr);
}

// round 14
// speedup vs baseline: 1.0778x; 1.0280x over previous
#include <cuda_runtime.h>
#include <cuda_bf16.h>
#include <cuda_fp16.h>

#define BB 4
#define CC 256
#define SS 4096
#define HH 4
#define DD 64
#define NROW (BB*SS)   // 16384

// scratch (allocation-free: __device__ globals)
__device__ float g_xt[NROW*CC];
__device__ float g_O[NROW*CC];     // attn out merged heads, tf32-rounded
__device__ float g_av[NROW*CC];
__device__ float g_avn[NROW*CC];   // ln2 out, tf32-rounded
__device__ float g_ff[NROW*CC];    // gelu(ff1), tf32-rounded
__device__ __half g_Qh[NROW*CC];   // [b,h,s,d] fp16, pre-scaled 0.125*log2e
__device__ __half g_Kh[NROW*CC];
__device__ __half g_Vh[NROW*CC];
__device__ float g_woT[CC*CC];
__device__ float g_w1T[CC*CC];
__device__ float g_w2T[CC*CC];

// ---------------- helpers ----------------
__device__ __forceinline__ unsigned smaddr(const void* p) {
    return (unsigned)__cvta_generic_to_shared(p);
}
__device__ __forceinline__ void ldsm4(unsigned &r0,unsigned &r1,unsigned &r2,unsigned &r3, unsigned a){
    asm volatile("ldmatrix.sync.aligned.m8n8.x4.shared.b16 {%0,%1,%2,%3}, [%4];"
        :"=r"(r0),"=r"(r1),"=r"(r2),"=r"(r3):"r"(a));
}
__device__ __forceinline__ void ldsm2t(unsigned &r0,unsigned &r1, unsigned a){
    asm volatile("ldmatrix.sync.aligned.m8n8.x2.trans.shared.b16 {%0,%1}, [%2];"
        :"=r"(r0),"=r"(r1):"r"(a));
}
__device__ __forceinline__ void ldsm4t(unsigned &r0,unsigned &r1,unsigned &r2,unsigned &r3, unsigned a){
    asm volatile("ldmatrix.sync.aligned.m8n8.x4.trans.shared.b16 {%0,%1,%2,%3}, [%4];"
        :"=r"(r0),"=r"(r1),"=r"(r2),"=r"(r3):"r"(a));
}
__device__ __forceinline__ void mmaf16(float c[4], const unsigned a[4], const unsigned b[2]){
    asm volatile("mma.sync.aligned.m16n8k16.row.col.f32.f16.f16.f32 "
        "{%0,%1,%2,%3},{%4,%5,%6,%7},{%8,%9},{%0,%1,%2,%3};"
        :"+f"(c[0]),"+f"(c[1]),"+f"(c[2]),"+f"(c[3])
        :"r"(a[0]),"r"(a[1]),"r"(a[2]),"r"(a[3]),"r"(b[0]),"r"(b[1]));
}
__device__ __forceinline__ void mma1688_tf32(float c[4], const unsigned a[4], const unsigned b[2]){
    asm volatile("mma.sync.aligned.m16n8k8.row.col.f32.tf32.tf32.f32 "
        "{%0,%1,%2,%3},{%4,%5,%6,%7},{%8,%9},{%0,%1,%2,%3};"
        :"+f"(c[0]),"+f"(c[1]),"+f"(c[2]),"+f"(c[3])
        :"r"(a[0]),"r"(a[1]),"r"(a[2]),"r"(a[3]),"r"(b[0]),"r"(b[1]));
}
// pack two f32 -> half2 {lo=a, hi=b}, then exp2 both halves in ONE MUFU op
__device__ __forceinline__ unsigned h2ex2(float a, float b){
    unsigned p, r;
    asm("cvt.rn.f16x2.f32 %0, %1, %2;" : "=r"(p) : "f"(b), "f"(a));
    asm("ex2.approx.f16x2 %0, %1;" : "=r"(r) : "r"(p));
    return r;
}
__device__ __forceinline__ float f2tf(float f){
    unsigned u;
    asm("cvt.rna.tf32.f32 %0, %1;" : "=r"(u) : "f"(f));
    return __uint_as_float(u);
}
__device__ __forceinline__ void cpa16(unsigned s, const void* g){
    asm volatile("cp.async.cg.shared.global [%0], [%1], 16;" :: "r"(s), "l"(g));
}
__device__ __forceinline__ void cpa_commit(){ asm volatile("cp.async.commit_group;"); }
template<int N> __device__ __forceinline__ void cpa_wait(){ asm volatile("cp.async.wait_group %0;" :: "n"(N)); }

// ---------------- K0b: round big weights to tf32 ----------------
__global__ void __launch_bounds__(256) k_wconv(const float* __restrict__ wo,
                                               const float* __restrict__ w1,
                                               const float* __restrict__ w2)
{
    int i = blockIdx.x*256 + threadIdx.x;
    g_woT[i] = f2tf(wo[i]);
    g_w1T[i] = f2tf(w1[i]);
    g_w2T[i] = f2tf(w2[i]);
}

// ---------------- K1: transpose + LN1 + QKV ----------------
#define LN1_SMEM ((256*33 + 3*4096 + 64) * 4)
__global__ void __launch_bounds__(256) k_ln1_qkv(
    const float* __restrict__ x,
    const float* __restrict__ g1, const float* __restrict__ b1,
    const float* __restrict__ wq, const float* __restrict__ bq,
    const float* __restrict__ wk, const float* __restrict__ bk,
    const float* __restrict__ wv, const float* __restrict__ bv)
{
    extern __shared__ float lsm[];
    float* tile = lsm;               // [256][33]
    float* wsq  = lsm + 256*33;      // [64][64]
    float* wsk  = wsq + 4096;
    float* wsv  = wsk + 4096;
    float* mu_s = wsv + 4096;        // [32]
    float* rs_s = mu_s + 32;         // [32]

    int t  = threadIdx.x;
    int s0 = blockIdx.x*32, b = blockIdx.y;
    int tx = t & 31, ty = t >> 5;

    for (int c = ty; c < 256; c += 8)
        tile[c*33 + tx] = x[((size_t)(b*CC) + c)*SS + s0 + tx];
    for (int i = t; i < 1024; i += 256) {
        ((float4*)wsq)[i] = ((const float4*)wq)[i];
        ((float4*)wsk)[i] = ((const float4*)wk)[i];
        ((float4*)wsv)[i] = ((const float4*)wv)[i];
    }
    __syncthreads();

    #pragma unroll 4
    for (int i = 0; i < 32; i++)
        g_xt[((size_t)(b*SS) + s0 + i)*CC + t] = tile[t*33 + i];

    {
        int si = t >> 3, g = t & 7;
        float su = 0.f, sq = 0.f;
        #pragma unroll 8
        for (int c = g*32; c < g*32 + 32; c++) {
            float v = tile[c*33 + si];
            su += v; sq += v*v;
        }
        #pragma unroll
        for (int o = 1; o < 8; o <<= 1) {
            su += __shfl_xor_sync(0xffffffffu, su, o);
            sq += __shfl_xor_sync(0xffffffffu, sq, o);
        }
        if (g == 0) {
            float mu = su * (1.0f/256.0f);
            float var = sq * (1.0f/256.0f) - mu*mu;
            mu_s[si] = mu;
            rs_s[si] = rsqrtf(var + 1e-5f);
        }
    }
    __syncthreads();

    for (int c = ty; c < 256; c += 8) {
        float gg = g1[c], bb = b1[c];
        float v = tile[c*33 + tx];
        tile[c*33 + tx] = (v - mu_s[tx]) * rs_s[tx] * gg + bb;
    }
    __syncthreads();

    int h = t >> 6, dd = t & 63;
    float bqv = bq[dd], bkv = bk[dd], bvv = bv[dd];
    const float* xb = tile + (h*64)*33;
    for (int sb = 0; sb < 32; sb += 8) {
        float aq[8], ak[8], av[8];
        #pragma unroll
        for (int u = 0; u < 8; u++) { aq[u]=bqv; ak[u]=bkv; av[u]=bvv; }
        #pragma unroll 4
        for (int j = 0; j < 64; j++) {
            float wqv = wsq[j*64+dd], wkv = wsk[j*64+dd], wvv2 = wsv[j*64+dd];
            const float* xr = xb + j*33 + sb;
            #pragma unroll
            for (int u = 0; u < 8; u++) {
                float xv = xr[u];
                aq[u] = fmaf(xv, wqv, aq[u]);
                ak[u] = fmaf(xv, wkv, ak[u]);
                av[u] = fmaf(xv, wvv2, av[u]);
            }
        }
        #pragma unroll
        for (int u = 0; u < 8; u++) {
            size_t o = (((size_t)(b*HH + h))*SS + s0 + sb + u)*DD + dd;
            g_Qh[o] = __float2half(aq[u] * 0.1803368801f);  // 0.125*log2(e)
            g_Kh[o] = __float2half(ak[u]);
            g_Vh[o] = __float2half(av[u]);
        }
    }
}

// ---------------- K2: flash attention fp16, f16x2 exp, ones-column l ----------------
#define KST 72
#define KVBUF (2*64*KST)
#define ATT_SMEM ((128*KST + 3*KVBUF) * 2)
__global__ void __launch_bounds__(256) k_attn()
{
    extern __shared__ __half sm[];
    __half* Qs = sm;
    __half* KV = sm + 128*KST;

    int blk = blockIdx.x;
    int bh  = blk >> 5;
    int qt  = blk & 31;
    const __half* Qp = g_Qh + (size_t)bh * SS * DD;
    const __half* Kp = g_Kh + (size_t)bh * SS * DD;
    const __half* Vp = g_Vh + (size_t)bh * SS * DD;
    int t = threadIdx.x, w = t >> 5, lane = t & 31;

    {
        const float4* Qg = (const float4*)(Qp + (size_t)qt*128*DD);
        #pragma unroll
        for (int i = t; i < 1024; i += 256) {
            int r = i >> 3, c = i & 7;
            *(float4*)(Qs + r*KST + c*8) = Qg[i];
        }
    }

    // init V cols 64..71 of all 3 buffers: col64 = 1.0h (l-column), rest 0
    if (t < 192) {
        int bufid = t >> 6;
        int row   = t & 63;
        uint4 ones = make_uint4(0x3C00u, 0u, 0u, 0u);
        *(uint4*)(KV + bufid*KVBUF + 64*KST + row*KST + 64) = ones;
    }

    #pragma unroll
    for (int pt = 0; pt < 2; pt++) {
        __half* Kb = KV + pt*KVBUF;
        __half* Vb = Kb + 64*KST;
        const __half* Kg = Kp + (size_t)pt*64*DD;
        const __half* Vg = Vp + (size_t)pt*64*DD;
        #pragma unroll
        for (int i = t; i < 512; i += 256) {
            int r = i >> 3, c = i & 7;
            cpa16(smaddr(Kb + r*KST + c*8), Kg + r*DD + c*8);
            cpa16(smaddr(Vb + r*KST + c*8), Vg + r*DD + c*8);
        }
        cpa_commit();
    }
    __syncthreads();

    unsigned qf[4][4];
    {
        int row  = w*16 + (lane & 15);
        int colb = (lane >> 4) * 8;
        #pragma unroll
        for (int c = 0; c < 4; c++) {
            unsigned a = smaddr(Qs + row*KST + c*16 + colb);
            ldsm4(qf[c][0], qf[c][1], qf[c][2], qf[c][3], a);
        }
    }

    float o[8][4];
    #pragma unroll
    for (int j = 0; j < 8; j++) { o[j][0]=0.f;o[j][1]=0.f;o[j][2]=0.f;o[j][3]=0.f; }
    float o8[4] = {0.f, 0.f, 0.f, 0.f};   // l accumulator block (V ones column)

    int buf = 0;
    for (int kt = 0; kt < 64; kt++) {
        if (kt < 63) cpa_wait<1>(); else cpa_wait<0>();
        __syncthreads();

        if (kt + 2 < 64) {
            int nb = buf + 2; if (nb >= 3) nb -= 3;
            __half* Kb = KV + nb*KVBUF;
            __half* Vb = Kb + 64*KST;
            const __half* Kg = Kp + (size_t)(kt+2)*64*DD;
            const __half* Vg = Vp + (size_t)(kt+2)*64*DD;
            #pragma unroll
            for (int i = t; i < 512; i += 256) {
                int r = i >> 3, c = i & 7;
                cpa16(smaddr(Kb + r*KST + c*8), Kg + r*DD + c*8);
                cpa16(smaddr(Vb + r*KST + c*8), Vg + r*DD + c*8);
            }
        }
        cpa_commit();

        const __half* Ks = KV + buf*KVBUF;
        const __half* Vs = Ks + 64*KST;

        // ---- S = Q K^T (log2-scaled), exp via f16x2 MUFU ----
        unsigned pa[4][4];
        #pragma unroll
        for (int j = 0; j < 8; j += 2) {
            float sA[4] = {0.f,0.f,0.f,0.f};
            float sB[4] = {0.f,0.f,0.f,0.f};
            #pragma unroll
            for (int c = 0; c < 4; c++) {
                unsigned kb[4];
                int krow = (j + ((lane>>4)&1))*8 + (lane&7);
                int kcol = c*16 + ((lane>>3)&1)*8;
                ldsm4(kb[0], kb[1], kb[2], kb[3], smaddr(Ks + krow*KST + kcol));
                mmaf16(sA, qf[c], kb);
                mmaf16(sB, qf[c], kb+2);
            }
            pa[j>>1][0] = h2ex2(sA[0], sA[1]);
            pa[j>>1][1] = h2ex2(sA[2], sA[3]);
            pa[j>>1][2] = h2ex2(sB[0], sB[1]);
            pa[j>>1][3] = h2ex2(sB[2], sB[3]);
        }

        // ---- O += P V (plus l via ones column) ----
        #pragma unroll
        for (int c2 = 0; c2 < 4; c2++) {
            #pragma unroll
            for (int j2 = 0; j2 < 8; j2 += 2) {
                unsigned vb[4];
                int vrow = c2*16 + (lane&15);
                int vcol = (j2 + ((lane>>4)&1))*8;
                ldsm4t(vb[0], vb[1], vb[2], vb[3], smaddr(Vs + vrow*KST + vcol));
                mmaf16(o[j2],   pa[c2], vb);
                mmaf16(o[j2+1], pa[c2], vb+2);
            }
            unsigned vb2[2];
            ldsm2t(vb2[0], vb2[1], smaddr(Vs + (c2*16 + (lane&15))*KST + 64));
            mmaf16(o8, pa[c2], vb2);
        }
        buf++; if (buf >= 3) buf = 0;
    }

    // l lives in o8[0]/o8[2] of the qq==0 thread of each quad
    float l0 = __shfl_sync(0xffffffffu, o8[0], lane & ~3);
    float l1 = __shfl_sync(0xffffffffu, o8[2], lane & ~3);

    float inv0 = 1.0f / l0, inv1 = 1.0f / l1;
    int g  = lane >> 2, qq = lane & 3;
    int b  = bh >> 2, h = bh & 3;
    int srow0 = qt*128 + w*16 + g;
    size_t base0 = ((size_t)(b*SS) + srow0)*CC + h*64;
    size_t base1 = ((size_t)(b*SS) + srow0 + 8)*CC + h*64;
    #pragma unroll
    for (int j2 = 0; j2 < 8; j2++) {
        *(float2*)(g_O + base0 + j2*8 + qq*2) = make_float2(f2tf(o[j2][0]*inv0), f2tf(o[j2][1]*inv0));
        *(float2*)(g_O + base1 + j2*8 + qq*2) = make_float2(f2tf(o[j2][2]*inv1), f2tf(o[j2][3]*inv1));
    }
}

// ---------------- tf32 GEMM: 64x256 tiles, 512 thr, 2-stage ring (2 CTAs/SM) ----------------
#define KCH2 32
#define A3F 36
#define B3F 264
#define ABUF (64*A3F)
#define BBUF (KCH2*B3F)
#define GEMM_SMEM (2*(ABUF + BBUF)*4)   // 86016 B -> 2 CTAs/SM

template<int MODE>
__global__ void __launch_bounds__(512) k_gemm(const float* __restrict__ A,
                                              const float* __restrict__ W,
                                              const float* __restrict__ bias,
                                              float* __restrict__ outp,
                                              const float* __restrict__ gamma,
                                              const float* __restrict__ beta)
{
    extern __shared__ char smraw[];
    float* As3 = (float*)smraw;               // 2 x [64][A3F]
    float* Bs3 = As3 + 2*ABUF;                // 2 x [KCH2][B3F]
    int t = threadIdx.x, w = t >> 5, lane = t & 31;
    int wm = w >> 2, wn = w & 3;
    int r0 = blockIdx.x * 64;

    #pragma unroll
    for (int pc = 0; pc < 2; pc++) {
        {
            int r = t >> 3, c = t & 7;
            cpa16(smaddr(As3 + pc*ABUF + r*A3F + c*4), A + (size_t)(r0 + r)*CC + pc*KCH2 + c*4);
        }
        #pragma unroll
        for (int u = 0; u < 4; u++) {
            int i = t + u*512;
            int k = i >> 6, c = i & 63;
            cpa16(smaddr(Bs3 + pc*BBUF + k*B3F + c*4), W + (size_t)(pc*KCH2 + k)*CC + c*4);
        }
        cpa_commit();
    }

    float acc[8][4];
    #pragma unroll
    for (int j = 0; j < 8; j++) { acc[j][0]=0.f;acc[j][1]=0.f;acc[j][2]=0.f;acc[j][3]=0.f; }

    int ar = lane >> 2, ac = lane & 3;
    int bk = lane & 3,  bn = lane >> 2;

    int buf = 0;
    for (int ch = 0; ch < 8; ch++) {
        if (ch < 7) cpa_wait<1>(); else cpa_wait<0>();
        __syncthreads();

        const float* As = As3 + buf*ABUF;
        const float* Bs = Bs3 + buf*BBUF;
        #pragma unroll
        for (int k8 = 0; k8 < KCH2; k8 += 8) {
            unsigned af[4];
            const float* ab = As + (wm*16 + ar)*A3F + k8 + ac;
            af[0] = __float_as_uint(ab[0]);
            af[1] = __float_as_uint(ab[8*A3F]);
            af[2] = __float_as_uint(ab[4]);
            af[3] = __float_as_uint(ab[8*A3F + 4]);
            #pragma unroll
            for (int j = 0; j < 8; j++) {
                unsigned bf[2];
                const float* bb = Bs + (k8 + bk)*B3F + wn*64 + j*8 + bn;
                bf[0] = __float_as_uint(bb[0]);
                bf[1] = __float_as_uint(bb[4*B3F]);
                mma1688_tf32(acc[j], af, bf);
            }
        }

        if (ch + 2 < 8) {
            __syncthreads();
            int kc = (ch+2)*KCH2;
            {
                int r = t >> 3, c = t & 7;
                cpa16(smaddr(As3 + buf*ABUF + r*A3F + c*4), A + (size_t)(r0 + r)*CC + kc + c*4);
            }
            #pragma unroll
            for (int u = 0; u < 4; u++) {
                int i = t + u*512;
                int k = i >> 6, c = i & 63;
                cpa16(smaddr(Bs3 + buf*BBUF + k*B3F + c*4), W + (size_t)(kc + k)*CC + c*4);
            }
        }
        cpa_commit();
        buf ^= 1;
    }

    int ml = wm*16 + (lane>>2);
    int rlo = r0 + ml, rhi = rlo + 8;

    if (MODE == 0) {
        #pragma unroll
        for (int j = 0; j < 8; j++) {
            int c = wn*64 + j*8 + (lane&3)*2;
            float2 bz = *(const float2*)(bias + c);
            float2 x0 = *(const float2*)(g_xt + (size_t)rlo*CC + c);
            float2 x1 = *(const float2*)(g_xt + (size_t)rhi*CC + c);
            acc[j][0] += bz.x + x0.x; acc[j][1] += bz.y + x0.y;
            acc[j][2] += bz.x + x1.x; acc[j][3] += bz.y + x1.y;
            *(float2*)(g_av + (size_t)rlo*CC + c) = make_float2(acc[j][0], acc[j][1]);
            *(float2*)(g_av + (size_t)rhi*CC + c) = make_float2(acc[j][2], acc[j][3]);
        }
        float sl = 0.f, ql = 0.f, sh = 0.f, qh = 0.f;
        #pragma unroll
        for (int j = 0; j < 8; j++) {
            sl += acc[j][0] + acc[j][1];
            ql += acc[j][0]*acc[j][0] + acc[j][1]*acc[j][1];
            sh += acc[j][2] + acc[j][3];
            qh += acc[j][2]*acc[j][2] + acc[j][3]*acc[j][3];
        }
        #pragma unroll
        for (int oo = 1; oo < 4; oo <<= 1) {
            sl += __shfl_xor_sync(0xffffffffu, sl, oo);
            ql += __shfl_xor_sync(0xffffffffu, ql, oo);
            sh += __shfl_xor_sync(0xffffffffu, sh, oo);
            qh += __shfl_xor_sync(0xffffffffu, qh, oo);
        }
        __syncthreads();
        float* red = (float*)smraw;   // [4 wn][64 rows][2]
        if ((lane & 3) == 0) {
            red[(wn*64 + ml)*2 + 0] = sl;
            red[(wn*64 + ml)*2 + 1] = ql;
            red[(wn*64 + ml + 8)*2 + 0] = sh;
            red[(wn*64 + ml + 8)*2 + 1] = qh;
        }
        __syncthreads();
        float suL=0.f, qL=0.f, suH=0.f, qH=0.f;
        #pragma unroll
        for (int z = 0; z < 4; z++) {
            suL += red[(z*64+ml)*2+0];   qL += red[(z*64+ml)*2+1];
            suH += red[(z*64+ml+8)*2+0]; qH += red[(z*64+ml+8)*2+1];
        }
        float muL = suL*(1.0f/256.0f), vaL = qL*(1.0f/256.0f) - muL*muL;
        float muH = suH*(1.0f/256.0f), vaH = qH*(1.0f/256.0f) - muH*muH;
        float rsL = rsqrtf(vaL + 1e-5f), rsH = rsqrtf(vaH + 1e-5f);
        #pragma unroll
        for (int j = 0; j < 8; j++) {
            int c = wn*64 + j*8 + (lane&3)*2;
            float2 gz = *(const float2*)(gamma + c);
            float2 bz = *(const float2*)(beta + c);
            float n0 = (acc[j][0]-muL)*rsL*gz.x + bz.x;
            float n1 = (acc[j][1]-muL)*rsL*gz.y + bz.y;
            float n2 = (acc[j][2]-muH)*rsH*gz.x + bz.x;
            float n3 = (acc[j][3]-muH)*rsH*gz.y + bz.y;
            *(float2*)(g_avn + (size_t)rlo*CC + c) = make_float2(f2tf(n0), f2tf(n1));
            *(float2*)(g_avn + (size_t)rhi*CC + c) = make_float2(f2tf(n2), f2tf(n3));
        }
    } else if (MODE == 1) {
        #pragma unroll
        for (int j = 0; j < 8; j++) {
            int c = wn*64 + j*8 + (lane&3)*2;
            float2 bz = *(const float2*)(bias + c);
            float f0 = acc[j][0]+bz.x, f1 = acc[j][1]+bz.y;
            float f2 = acc[j][2]+bz.x, f3 = acc[j][3]+bz.y;
            float g0 = 0.5f*f0*(1.0f+erff(f0*0.70710678118654752f));
            float g1 = 0.5f*f1*(1.0f+erff(f1*0.70710678118654752f));
            float g2 = 0.5f*f2*(1.0f+erff(f2*0.70710678118654752f));
            float g3 = 0.5f*f3*(1.0f+erff(f3*0.70710678118654752f));
            *(float2*)(g_ff + (size_t)rlo*CC + c) = make_float2(f2tf(g0), f2tf(g1));
            *(float2*)(g_ff + (size_t)rhi*CC + c) = make_float2(f2tf(g2), f2tf(g3));
        }
    } else {
        __syncthreads();
        float* Ts = (float*)smraw;   // [256][65] = 66560 B <= 86016
        #pragma unroll
        for (int j = 0; j < 8; j++) {
            int c = wn*64 + j*8 + (lane&3)*2;
            float2 bz = *(const float2*)(bias + c);
            float2 a0 = *(const float2*)(g_av + (size_t)rlo*CC + c);
            float2 a1 = *(const float2*)(g_av + (size_t)rhi*CC + c);
            Ts[(c+0)*65 + ml]     = acc[j][0]+bz.x+a0.x;
            Ts[(c+1)*65 + ml]     = acc[j][1]+bz.y+a0.y;
            Ts[(c+0)*65 + ml + 8] = acc[j][2]+bz.x+a1.x;
            Ts[(c+1)*65 + ml + 8] = acc[j][3]+bz.y+a1.y;
        }
        __syncthreads();
        int b  = r0 >> 12;
        int s0 = r0 & 4095;
        for (int i = t; i < 16384; i += 512) {
            int c = i >> 6, r = i & 63;
            outp[((size_t)(b*CC) + c)*SS + s0 + r] = Ts[c*65 + r];
        }
    }
}

extern "C" void kernel_launch(void* const* d_in, const int* in_sizes, int n_in,
                              void* d_out, int out_size)
{
    const float* x     = (const float*)d_in[0];
    const float* ln1_g = (const float*)d_in[1];
    const float* ln1_b = (const float*)d_in[2];
    const float* wq    = (const float*)d_in[3];
    const float* bq    = (const float*)d_in[4];
    const float* wk    = (const float*)d_in[5];
    const float* bk    = (const float*)d_in[6];
    const float* wv    = (const float*)d_in[7];
    const float* bv    = (const float*)d_in[8];
    const float* wo    = (const float*)d_in[9];
    const float* bo    = (const float*)d_in[10];
    const float* ln2_g = (const float*)d_in[11];
    const float* ln2_b = (const float*)d_in[12];
    const float* w1    = (const float*)d_in[13];
    const float* b1    = (const float*)d_in[14];
    const float* w2    = (const float*)d_in[15];
    const float* b2    = (const float*)d_in[16];
    float* out = (float*)d_out;

    cudaFuncSetAttribute(k_ln1_qkv, cudaFuncAttributeMaxDynamicSharedMemorySize, LN1_SMEM);
    cudaFuncSetAttribute(k_attn,    cudaFuncAttributeMaxDynamicSharedMemorySize, ATT_SMEM);
    cudaFuncSetAttribute(k_gemm<0>, cudaFuncAttributeMaxDynamicSharedMemorySize, GEMM_SMEM);
    cudaFuncSetAttribute(k_gemm<1>, cudaFuncAttributeMaxDynamicSharedMemorySize, GEMM_SMEM);
    cudaFuncSetAttribute(k_gemm<2>, cudaFuncAttributeMaxDynamicSharedMemorySize, GEMM_SMEM);

    float* woT; cudaGetSymbolAddress((void**)&woT, g_woT);
    float* w1T; cudaGetSymbolAddress((void**)&w1T, g_w1T);
    float* w2T; cudaGetSymbolAddress((void**)&w2T, g_w2T);
    float* O;   cudaGetSymbolAddress((void**)&O,   g_O);
    float* avn; cudaGetSymbolAddress((void**)&avn, g_avn);
    float* ff;  cudaGetSymbolAddress((void**)&ff,  g_ff);

    k_wconv<<<256, 256>>>(wo, w1, w2);
    k_ln1_qkv<<<dim3(SS/32, BB), 256, LN1_SMEM>>>(x, ln1_g, ln1_b, wq, bq, wk, bk, wv, bv);
    k_attn<<<BB*HH*(SS/128), 256, ATT_SMEM>>>();
    k_gemm<0><<<NROW/64, 512, GEMM_SMEM>>>(O,   woT, bo, nullptr, ln2_g, ln2_b);
    k_gemm<1><<<NROW/64, 512, GEMM_SMEM>>>(avn, w1T, b1, nullptr, nullptr, nullptr);
    k_gemm<2><<<NROW/64, 512, GEMM_SMEM>>>(ff,  w2T, b2, out,     nullptr, nullptr);
}

// round 15
// speedup vs baseline: 1.1499x; 1.0668x over previous
#include <cuda_runtime.h>
#include <cuda_bf16.h>
#include <cuda_fp16.h>

#define BB 4
#define CC 256
#define SS 4096
#define HH 4
#define DD 64
#define NROW (BB*SS)   // 16384

// scratch (allocation-free: __device__ globals)
__device__ float g_xt[NROW*CC];      // transposed input, fp32 (residual)
__device__ float g_av[NROW*CC];      // residual1, fp32
__device__ __half g_Oh2[NROW*CC];    // attn out merged heads, fp16
__device__ __half g_avnh[NROW*CC];   // ln2 out, fp16
__device__ __half g_ffh[NROW*CC];    // gelu(ff1), fp16
__device__ __half g_Qh[NROW*CC];     // [b,h,s,d] fp16, pre-scaled 0.125*log2e
__device__ __half g_Kh[NROW*CC];
__device__ __half g_Vh[NROW*CC];
__device__ __half g_woH[CC*CC];      // fp16 weights
__device__ __half g_w1H[CC*CC];
__device__ __half g_w2H[CC*CC];

// ---------------- helpers ----------------
__device__ __forceinline__ unsigned smaddr(const void* p) {
    return (unsigned)__cvta_generic_to_shared(p);
}
__device__ __forceinline__ void ldsm4(unsigned &r0,unsigned &r1,unsigned &r2,unsigned &r3, unsigned a){
    asm volatile("ldmatrix.sync.aligned.m8n8.x4.shared.b16 {%0,%1,%2,%3}, [%4];"
        :"=r"(r0),"=r"(r1),"=r"(r2),"=r"(r3):"r"(a));
}
__device__ __forceinline__ void ldsm2t(unsigned &r0,unsigned &r1, unsigned a){
    asm volatile("ldmatrix.sync.aligned.m8n8.x2.trans.shared.b16 {%0,%1}, [%2];"
        :"=r"(r0),"=r"(r1):"r"(a));
}
__device__ __forceinline__ void ldsm4t(unsigned &r0,unsigned &r1,unsigned &r2,unsigned &r3, unsigned a){
    asm volatile("ldmatrix.sync.aligned.m8n8.x4.trans.shared.b16 {%0,%1,%2,%3}, [%4];"
        :"=r"(r0),"=r"(r1),"=r"(r2),"=r"(r3):"r"(a));
}
__device__ __forceinline__ void mmaf16(float c[4], const unsigned a[4], const unsigned b[2]){
    asm volatile("mma.sync.aligned.m16n8k16.row.col.f32.f16.f16.f32 "
        "{%0,%1,%2,%3},{%4,%5,%6,%7},{%8,%9},{%0,%1,%2,%3};"
        :"+f"(c[0]),"+f"(c[1]),"+f"(c[2]),"+f"(c[3])
        :"r"(a[0]),"r"(a[1]),"r"(a[2]),"r"(a[3]),"r"(b[0]),"r"(b[1]));
}
// pack two f32 -> half2 {lo=a, hi=b}
__device__ __forceinline__ unsigned h2pack(float a, float b){
    unsigned p;
    asm("cvt.rn.f16x2.f32 %0, %1, %2;" : "=r"(p) : "f"(b), "f"(a));
    return p;
}
// pack + exp2 both halves in one MUFU op
__device__ __forceinline__ unsigned h2ex2(float a, float b){
    unsigned p, r;
    asm("cvt.rn.f16x2.f32 %0, %1, %2;" : "=r"(p) : "f"(b), "f"(a));
    asm("ex2.approx.f16x2 %0, %1;" : "=r"(r) : "r"(p));
    return r;
}
__device__ __forceinline__ void cpa16(unsigned s, const void* g){
    asm volatile("cp.async.cg.shared.global [%0], [%1], 16;" :: "r"(s), "l"(g));
}
__device__ __forceinline__ void cpa_commit(){ asm volatile("cp.async.commit_group;"); }
template<int N> __device__ __forceinline__ void cpa_wait(){ asm volatile("cp.async.wait_group %0;" :: "n"(N)); }

// ---------------- K0b: convert big weights to fp16 ----------------
__global__ void __launch_bounds__(256) k_wconv(const float* __restrict__ wo,
                                               const float* __restrict__ w1,
                                               const float* __restrict__ w2)
{
    int i = blockIdx.x*256 + threadIdx.x;
    g_woH[i] = __float2half(wo[i]);
    g_w1H[i] = __float2half(w1[i]);
    g_w2H[i] = __float2half(w2[i]);
}

// ---------------- K1: transpose + LN1 + QKV ----------------
#define LN1_SMEM ((256*33 + 3*4096 + 64) * 4)
__global__ void __launch_bounds__(256) k_ln1_qkv(
    const float* __restrict__ x,
    const float* __restrict__ g1, const float* __restrict__ b1,
    const float* __restrict__ wq, const float* __restrict__ bq,
    const float* __restrict__ wk, const float* __restrict__ bk,
    const float* __restrict__ wv, const float* __restrict__ bv)
{
    extern __shared__ float lsm[];
    float* tile = lsm;               // [256][33]
    float* wsq  = lsm + 256*33;      // [64][64]
    float* wsk  = wsq + 4096;
    float* wsv  = wsk + 4096;
    float* mu_s = wsv + 4096;        // [32]
    float* rs_s = mu_s + 32;         // [32]

    int t  = threadIdx.x;
    int s0 = blockIdx.x*32, b = blockIdx.y;
    int tx = t & 31, ty = t >> 5;

    for (int c = ty; c < 256; c += 8)
        tile[c*33 + tx] = x[((size_t)(b*CC) + c)*SS + s0 + tx];
    for (int i = t; i < 1024; i += 256) {
        ((float4*)wsq)[i] = ((const float4*)wq)[i];
        ((float4*)wsk)[i] = ((const float4*)wk)[i];
        ((float4*)wsv)[i] = ((const float4*)wv)[i];
    }
    __syncthreads();

    #pragma unroll 4
    for (int i = 0; i < 32; i++)
        g_xt[((size_t)(b*SS) + s0 + i)*CC + t] = tile[t*33 + i];

    {
        int si = t >> 3, g = t & 7;
        float su = 0.f, sq = 0.f;
        #pragma unroll 8
        for (int c = g*32; c < g*32 + 32; c++) {
            float v = tile[c*33 + si];
            su += v; sq += v*v;
        }
        #pragma unroll
        for (int o = 1; o < 8; o <<= 1) {
            su += __shfl_xor_sync(0xffffffffu, su, o);
            sq += __shfl_xor_sync(0xffffffffu, sq, o);
        }
        if (g == 0) {
            float mu = su * (1.0f/256.0f);
            float var = sq * (1.0f/256.0f) - mu*mu;
            mu_s[si] = mu;
            rs_s[si] = rsqrtf(var + 1e-5f);
        }
    }
    __syncthreads();

    for (int c = ty; c < 256; c += 8) {
        float gg = g1[c], bb = b1[c];
        float v = tile[c*33 + tx];
        tile[c*33 + tx] = (v - mu_s[tx]) * rs_s[tx] * gg + bb;
    }
    __syncthreads();

    int h = t >> 6, dd = t & 63;
    float bqv = bq[dd], bkv = bk[dd], bvv = bv[dd];
    const float* xb = tile + (h*64)*33;
    for (int sb = 0; sb < 32; sb += 8) {
        float aq[8], ak[8], av[8];
        #pragma unroll
        for (int u = 0; u < 8; u++) { aq[u]=bqv; ak[u]=bkv; av[u]=bvv; }
        #pragma unroll 4
        for (int j = 0; j < 64; j++) {
            float wqv = wsq[j*64+dd], wkv = wsk[j*64+dd], wvv2 = wsv[j*64+dd];
            const float* xr = xb + j*33 + sb;
            #pragma unroll
            for (int u = 0; u < 8; u++) {
                float xv = xr[u];
                aq[u] = fmaf(xv, wqv, aq[u]);
                ak[u] = fmaf(xv, wkv, ak[u]);
                av[u] = fmaf(xv, wvv2, av[u]);
            }
        }
        #pragma unroll
        for (int u = 0; u < 8; u++) {
            size_t o = (((size_t)(b*HH + h))*SS + s0 + sb + u)*DD + dd;
            g_Qh[o] = __float2half(aq[u] * 0.1803368801f);  // 0.125*log2(e)
            g_Kh[o] = __float2half(ak[u]);
            g_Vh[o] = __float2half(av[u]);
        }
    }
}

// ---------------- K2: flash attention fp16, f16x2 exp, ones-column l ----------------
#define KST 72
#define KVBUF (2*64*KST)
#define ATT_SMEM ((128*KST + 3*KVBUF) * 2)
__global__ void __launch_bounds__(256) k_attn()
{
    extern __shared__ __half sm[];
    __half* Qs = sm;
    __half* KV = sm + 128*KST;

    int blk = blockIdx.x;
    int bh  = blk >> 5;
    int qt  = blk & 31;
    const __half* Qp = g_Qh + (size_t)bh * SS * DD;
    const __half* Kp = g_Kh + (size_t)bh * SS * DD;
    const __half* Vp = g_Vh + (size_t)bh * SS * DD;
    int t = threadIdx.x, w = t >> 5, lane = t & 31;

    {
        const float4* Qg = (const float4*)(Qp + (size_t)qt*128*DD);
        #pragma unroll
        for (int i = t; i < 1024; i += 256) {
            int r = i >> 3, c = i & 7;
            *(float4*)(Qs + r*KST + c*8) = Qg[i];
        }
    }

    // init V cols 64..71 of all 3 buffers: col64 = 1.0h (l-column), rest 0
    if (t < 192) {
        int bufid = t >> 6;
        int row   = t & 63;
        uint4 ones = make_uint4(0x3C00u, 0u, 0u, 0u);
        *(uint4*)(KV + bufid*KVBUF + 64*KST + row*KST + 64) = ones;
    }

    #pragma unroll
    for (int pt = 0; pt < 2; pt++) {
        __half* Kb = KV + pt*KVBUF;
        __half* Vb = Kb + 64*KST;
        const __half* Kg = Kp + (size_t)pt*64*DD;
        const __half* Vg = Vp + (size_t)pt*64*DD;
        #pragma unroll
        for (int i = t; i < 512; i += 256) {
            int r = i >> 3, c = i & 7;
            cpa16(smaddr(Kb + r*KST + c*8), Kg + r*DD + c*8);
            cpa16(smaddr(Vb + r*KST + c*8), Vg + r*DD + c*8);
        }
        cpa_commit();
    }
    __syncthreads();

    unsigned qf[4][4];
    {
        int row  = w*16 + (lane & 15);
        int colb = (lane >> 4) * 8;
        #pragma unroll
        for (int c = 0; c < 4; c++) {
            unsigned a = smaddr(Qs + row*KST + c*16 + colb);
            ldsm4(qf[c][0], qf[c][1], qf[c][2], qf[c][3], a);
        }
    }

    float o[8][4];
    #pragma unroll
    for (int j = 0; j < 8; j++) { o[j][0]=0.f;o[j][1]=0.f;o[j][2]=0.f;o[j][3]=0.f; }
    float o8[4] = {0.f, 0.f, 0.f, 0.f};   // l accumulator block (V ones column)

    int buf = 0;
    for (int kt = 0; kt < 64; kt++) {
        if (kt < 63) cpa_wait<1>(); else cpa_wait<0>();
        __syncthreads();

        if (kt + 2 < 64) {
            int nb = buf + 2; if (nb >= 3) nb -= 3;
            __half* Kb = KV + nb*KVBUF;
            __half* Vb = Kb + 64*KST;
            const __half* Kg = Kp + (size_t)(kt+2)*64*DD;
            const __half* Vg = Vp + (size_t)(kt+2)*64*DD;
            #pragma unroll
            for (int i = t; i < 512; i += 256) {
                int r = i >> 3, c = i & 7;
                cpa16(smaddr(Kb + r*KST + c*8), Kg + r*DD + c*8);
                cpa16(smaddr(Vb + r*KST + c*8), Vg + r*DD + c*8);
            }
        }
        cpa_commit();

        const __half* Ks = KV + buf*KVBUF;
        const __half* Vs = Ks + 64*KST;

        unsigned pa[4][4];
        #pragma unroll
        for (int j = 0; j < 8; j += 2) {
            float sA[4] = {0.f,0.f,0.f,0.f};
            float sB[4] = {0.f,0.f,0.f,0.f};
            #pragma unroll
            for (int c = 0; c < 4; c++) {
                unsigned kb[4];
                int krow = (j + ((lane>>4)&1))*8 + (lane&7);
                int kcol = c*16 + ((lane>>3)&1)*8;
                ldsm4(kb[0], kb[1], kb[2], kb[3], smaddr(Ks + krow*KST + kcol));
                mmaf16(sA, qf[c], kb);
                mmaf16(sB, qf[c], kb+2);
            }
            pa[j>>1][0] = h2ex2(sA[0], sA[1]);
            pa[j>>1][1] = h2ex2(sA[2], sA[3]);
            pa[j>>1][2] = h2ex2(sB[0], sB[1]);
            pa[j>>1][3] = h2ex2(sB[2], sB[3]);
        }

        #pragma unroll
        for (int c2 = 0; c2 < 4; c2++) {
            #pragma unroll
            for (int j2 = 0; j2 < 8; j2 += 2) {
                unsigned vb[4];
                int vrow = c2*16 + (lane&15);
                int vcol = (j2 + ((lane>>4)&1))*8;
                ldsm4t(vb[0], vb[1], vb[2], vb[3], smaddr(Vs + vrow*KST + vcol));
                mmaf16(o[j2],   pa[c2], vb);
                mmaf16(o[j2+1], pa[c2], vb+2);
            }
            unsigned vb2[2];
            ldsm2t(vb2[0], vb2[1], smaddr(Vs + (c2*16 + (lane&15))*KST + 64));
            mmaf16(o8, pa[c2], vb2);
        }
        buf++; if (buf >= 3) buf = 0;
    }

    float l0 = __shfl_sync(0xffffffffu, o8[0], lane & ~3);
    float l1 = __shfl_sync(0xffffffffu, o8[2], lane & ~3);

    float inv0 = 1.0f / l0, inv1 = 1.0f / l1;
    int g  = lane >> 2, qq = lane & 3;
    int b  = bh >> 2, h = bh & 3;
    int srow0 = qt*128 + w*16 + g;
    size_t base0 = ((size_t)(b*SS) + srow0)*CC + h*64;
    size_t base1 = ((size_t)(b*SS) + srow0 + 8)*CC + h*64;
    #pragma unroll
    for (int j2 = 0; j2 < 8; j2++) {
        *(unsigned*)(g_Oh2 + base0 + j2*8 + qq*2) = h2pack(o[j2][0]*inv0, o[j2][1]*inv0);
        *(unsigned*)(g_Oh2 + base1 + j2*8 + qq*2) = h2pack(o[j2][2]*inv1, o[j2][3]*inv1);
    }
}

// ---------------- fp16 GEMM: 64x256 tiles, 512 thr, 2-stage cp.async ring ----------------
// MODE 0: +bias +g_xt residual -> g_av(fp32), LN2 -> g_avnh(fp16)
// MODE 1: +bias, gelu -> g_ffh(fp16)
// MODE 2: +bias +g_av residual -> out fp32 transposed [b][c][s]
#define KCH2 32
#define AHST 40          // half stride: 32+8, conflict-free ldsm4
#define BHST 264         // half stride: 256+8, conflict-free ldsm4t
#define ABUFH (64*AHST)  // halves
#define BBUFH (KCH2*BHST)
#define GEMM_SMEM01 (2*(ABUFH + BBUFH)*2)   // 44032 B
#define GEMM_SMEM2  (256*65*4)              // 66560 B (transpose epilogue)

template<int MODE>
__global__ void __launch_bounds__(512) k_gemm(const __half* __restrict__ A,
                                              const __half* __restrict__ W,
                                              const float* __restrict__ bias,
                                              float* __restrict__ outp,
                                              const float* __restrict__ gamma,
                                              const float* __restrict__ beta)
{
    extern __shared__ char smraw[];
    __half* As2 = (__half*)smraw;             // 2 x [64][AHST]
    __half* Bs2 = As2 + 2*ABUFH;              // 2 x [KCH2][BHST]
    int t = threadIdx.x, w = t >> 5, lane = t & 31;
    int wm = w >> 2, wn = w & 3;
    int r0 = blockIdx.x * 64;

    // prologue: chunks 0,1 into bufs 0,1
    #pragma unroll
    for (int pc = 0; pc < 2; pc++) {
        if (t < 256) {
            int r = t >> 2, c = t & 3;
            cpa16(smaddr(As2 + pc*ABUFH + r*AHST + c*8), A + (size_t)(r0 + r)*CC + pc*KCH2 + c*8);
        }
        #pragma unroll
        for (int u = 0; u < 2; u++) {
            int i = t + u*512;
            int k = i >> 5, c = i & 31;
            cpa16(smaddr(Bs2 + pc*BBUFH + k*BHST + c*8), W + (size_t)(pc*KCH2 + k)*CC + c*8);
        }
        cpa_commit();
    }

    float acc[8][4];
    #pragma unroll
    for (int j = 0; j < 8; j++) { acc[j][0]=0.f;acc[j][1]=0.f;acc[j][2]=0.f;acc[j][3]=0.f; }

    int buf = 0;
    for (int ch = 0; ch < 8; ch++) {
        if (ch < 7) cpa_wait<1>(); else cpa_wait<0>();
        __syncthreads();

        const __half* As = As2 + buf*ABUFH;
        const __half* Bs = Bs2 + buf*BBUFH;
        #pragma unroll
        for (int k8 = 0; k8 < KCH2; k8 += 16) {
            unsigned af[4];
            ldsm4(af[0], af[1], af[2], af[3],
                  smaddr(As + (wm*16 + (lane&15))*AHST + k8 + (lane>>4)*8));
            #pragma unroll
            for (int j = 0; j < 8; j += 2) {
                unsigned bf[4];
                int brow = k8 + (lane&15);
                int bcol = wn*64 + (j + ((lane>>4)&1))*8;
                ldsm4t(bf[0], bf[1], bf[2], bf[3], smaddr(Bs + brow*BHST + bcol));
                mmaf16(acc[j],   af, bf);
                mmaf16(acc[j+1], af, bf+2);
            }
        }

        // refill this buffer with chunk ch+2 (after all warps finished reading it)
        if (ch + 2 < 8) {
            __syncthreads();
            int kc = (ch+2)*KCH2;
            if (t < 256) {
                int r = t >> 2, c = t & 3;
                cpa16(smaddr(As2 + buf*ABUFH + r*AHST + c*8), A + (size_t)(r0 + r)*CC + kc + c*8);
            }
            #pragma unroll
            for (int u = 0; u < 2; u++) {
                int i = t + u*512;
                int k = i >> 5, c = i & 31;
                cpa16(smaddr(Bs2 + buf*BBUFH + k*BHST + c*8), W + (size_t)(kc + k)*CC + c*8);
            }
        }
        cpa_commit();
        buf ^= 1;
    }

    int ml = wm*16 + (lane>>2);
    int rlo = r0 + ml, rhi = rlo + 8;

    if (MODE == 0) {
        #pragma unroll
        for (int j = 0; j < 8; j++) {
            int c = wn*64 + j*8 + (lane&3)*2;
            float2 bz = *(const float2*)(bias + c);
            float2 x0 = *(const float2*)(g_xt + (size_t)rlo*CC + c);
            float2 x1 = *(const float2*)(g_xt + (size_t)rhi*CC + c);
            acc[j][0] += bz.x + x0.x; acc[j][1] += bz.y + x0.y;
            acc[j][2] += bz.x + x1.x; acc[j][3] += bz.y + x1.y;
            *(float2*)(g_av + (size_t)rlo*CC + c) = make_float2(acc[j][0], acc[j][1]);
            *(float2*)(g_av + (size_t)rhi*CC + c) = make_float2(acc[j][2], acc[j][3]);
        }
        float sl = 0.f, ql = 0.f, sh = 0.f, qh = 0.f;
        #pragma unroll
        for (int j = 0; j < 8; j++) {
            sl += acc[j][0] + acc[j][1];
            ql += acc[j][0]*acc[j][0] + acc[j][1]*acc[j][1];
            sh += acc[j][2] + acc[j][3];
            qh += acc[j][2]*acc[j][2] + acc[j][3]*acc[j][3];
        }
        #pragma unroll
        for (int oo = 1; oo < 4; oo <<= 1) {
            sl += __shfl_xor_sync(0xffffffffu, sl, oo);
            ql += __shfl_xor_sync(0xffffffffu, ql, oo);
            sh += __shfl_xor_sync(0xffffffffu, sh, oo);
            qh += __shfl_xor_sync(0xffffffffu, qh, oo);
        }
        __syncthreads();
        float* red = (float*)smraw;   // [4 wn][64 rows][2]
        if ((lane & 3) == 0) {
            red[(wn*64 + ml)*2 + 0] = sl;
            red[(wn*64 + ml)*2 + 1] = ql;
            red[(wn*64 + ml + 8)*2 + 0] = sh;
            red[(wn*64 + ml + 8)*2 + 1] = qh;
        }
        __syncthreads();
        float suL=0.f, qL=0.f, suH=0.f, qH=0.f;
        #pragma unroll
        for (int z = 0; z < 4; z++) {
            suL += red[(z*64+ml)*2+0];   qL += red[(z*64+ml)*2+1];
            suH += red[(z*64+ml+8)*2+0]; qH += red[(z*64+ml+8)*2+1];
        }
        float muL = suL*(1.0f/256.0f), vaL = qL*(1.0f/256.0f) - muL*muL;
        float muH = suH*(1.0f/256.0f), vaH = qH*(1.0f/256.0f) - muH*muH;
        float rsL = rsqrtf(vaL + 1e-5f), rsH = rsqrtf(vaH + 1e-5f);
        #pragma unroll
        for (int j = 0; j < 8; j++) {
            int c = wn*64 + j*8 + (lane&3)*2;
            float2 gz = *(const float2*)(gamma + c);
            float2 bz = *(const float2*)(beta + c);
            float n0 = (acc[j][0]-muL)*rsL*gz.x + bz.x;
            float n1 = (acc[j][1]-muL)*rsL*gz.y + bz.y;
            float n2 = (acc[j][2]-muH)*rsH*gz.x + bz.x;
            float n3 = (acc[j][3]-muH)*rsH*gz.y + bz.y;
            *(unsigned*)(g_avnh + (size_t)rlo*CC + c) = h2pack(n0, n1);
            *(unsigned*)(g_avnh + (size_t)rhi*CC + c) = h2pack(n2, n3);
        }
    } else if (MODE == 1) {
        #pragma unroll
        for (int j = 0; j < 8; j++) {
            int c = wn*64 + j*8 + (lane&3)*2;
            float2 bz = *(const float2*)(bias + c);
            float f0 = acc[j][0]+bz.x, f1 = acc[j][1]+bz.y;
            float f2 = acc[j][2]+bz.x, f3 = acc[j][3]+bz.y;
            float g0 = 0.5f*f0*(1.0f+erff(f0*0.70710678118654752f));
            float g1 = 0.5f*f1*(1.0f+erff(f1*0.70710678118654752f));
            float g2 = 0.5f*f2*(1.0f+erff(f2*0.70710678118654752f));
            float g3 = 0.5f*f3*(1.0f+erff(f3*0.70710678118654752f));
            *(unsigned*)(g_ffh + (size_t)rlo*CC + c) = h2pack(g0, g1);
            *(unsigned*)(g_ffh + (size_t)rhi*CC + c) = h2pack(g2, g3);
        }
    } else {
        __syncthreads();
        float* Ts = (float*)smraw;   // [256][65] = 66560 B
        #pragma unroll
        for (int j = 0; j < 8; j++) {
            int c = wn*64 + j*8 + (lane&3)*2;
            float2 bz = *(const float2*)(bias + c);
            float2 a0 = *(const float2*)(g_av + (size_t)rlo*CC + c);
            float2 a1 = *(const float2*)(g_av + (size_t)rhi*CC + c);
            Ts[(c+0)*65 + ml]     = acc[j][0]+bz.x+a0.x;
            Ts[(c+1)*65 + ml]     = acc[j][1]+bz.y+a0.y;
            Ts[(c+0)*65 + ml + 8] = acc[j][2]+bz.x+a1.x;
            Ts[(c+1)*65 + ml + 8] = acc[j][3]+bz.y+a1.y;
        }
        __syncthreads();
        int b  = r0 >> 12;
        int s0 = r0 & 4095;
        for (int i = t; i < 16384; i += 512) {
            int c = i >> 6, r = i & 63;
            outp[((size_t)(b*CC) + c)*SS + s0 + r] = Ts[c*65 + r];
        }
    }
}

extern "C" void kernel_launch(void* const* d_in, const int* in_sizes, int n_in,
                              void* d_out, int out_size)
{
    const float* x     = (const float*)d_in[0];
    const float* ln1_g = (const float*)d_in[1];
    const float* ln1_b = (const float*)d_in[2];
    const float* wq    = (const float*)d_in[3];
    const float* bq    = (const float*)d_in[4];
    const float* wk    = (const float*)d_in[5];
    const float* bk    = (const float*)d_in[6];
    const float* wv    = (const float*)d_in[7];
    const float* bv    = (const float*)d_in[8];
    const float* wo    = (const float*)d_in[9];
    const float* bo    = (const float*)d_in[10];
    const float* ln2_g = (const float*)d_in[11];
    const float* ln2_b = (const float*)d_in[12];
    const float* w1    = (const float*)d_in[13];
    const float* b1    = (const float*)d_in[14];
    const float* w2    = (const float*)d_in[15];
    const float* b2    = (const float*)d_in[16];
    float* out = (float*)d_out;

    cudaFuncSetAttribute(k_ln1_qkv, cudaFuncAttributeMaxDynamicSharedMemorySize, LN1_SMEM);
    cudaFuncSetAttribute(k_attn,    cudaFuncAttributeMaxDynamicSharedMemorySize, ATT_SMEM);
    cudaFuncSetAttribute(k_gemm<0>, cudaFuncAttributeMaxDynamicSharedMemorySize, GEMM_SMEM01);
    cudaFuncSetAttribute(k_gemm<1>, cudaFuncAttributeMaxDynamicSharedMemorySize, GEMM_SMEM01);
    cudaFuncSetAttribute(k_gemm<2>, cudaFuncAttributeMaxDynamicSharedMemorySize, GEMM_SMEM2);

    __half* woH; cudaGetSymbolAddress((void**)&woH, g_woH);
    __half* w1H; cudaGetSymbolAddress((void**)&w1H, g_w1H);
    __half* w2H; cudaGetSymbolAddress((void**)&w2H, g_w2H);
    __half* Oh;  cudaGetSymbolAddress((void**)&Oh,  g_Oh2);
    __half* avn; cudaGetSymbolAddress((void**)&avn, g_avnh);
    __half* ff;  cudaGetSymbolAddress((void**)&ff,  g_ffh);

    k_wconv<<<256, 256>>>(wo, w1, w2);
    k_ln1_qkv<<<dim3(SS/32, BB), 256, LN1_SMEM>>>(x, ln1_g, ln1_b, wq, bq, wk, bk, wv, bv);
    k_attn<<<BB*HH*(SS/128), 256, ATT_SMEM>>>();
    k_gemm<0><<<NROW/64, 512, GEMM_SMEM01>>>(Oh,  woH, bo, nullptr, ln2_g, ln2_b);
    k_gemm<1><<<NROW/64, 512, GEMM_SMEM01>>>(avn, w1H, b1, nullptr, nullptr, nullptr);
    k_gemm<2><<<NROW/64, 512, GEMM_SMEM2>>>(ff,  w2H, b2, out,     nullptr, nullptr);
}

// round 16
// speedup vs baseline: 1.1615x; 1.0101x over previous
#include <cuda_runtime.h>
#include <cuda_bf16.h>
#include <cuda_fp16.h>

#define BB 4
#define CC 256
#define SS 4096
#define HH 4
#define DD 64
#define NROW (BB*SS)   // 16384

// scratch (allocation-free: __device__ globals)
__device__ float g_xt[NROW*CC];      // transposed input, fp32 (residual)
__device__ float g_av[NROW*CC];      // residual1, fp32
__device__ __half g_Oh2[NROW*CC];    // attn out merged heads, fp16
__device__ __half g_avnh[NROW*CC];   // ln2 out, fp16
__device__ __half g_ffh[NROW*CC];    // gelu(ff1), fp16
__device__ __half g_Qh[NROW*CC];     // [b,h,s,d] fp16, pre-scaled 0.125*log2e
__device__ __half g_Kh[NROW*CC];
__device__ __half g_Vh[NROW*CC];
__device__ __half g_woH[CC*CC];      // fp16 weights
__device__ __half g_w1H[CC*CC];
__device__ __half g_w2H[CC*CC];

// ---------------- helpers ----------------
__device__ __forceinline__ unsigned smaddr(const void* p) {
    return (unsigned)__cvta_generic_to_shared(p);
}
__device__ __forceinline__ void ldsm4(unsigned &r0,unsigned &r1,unsigned &r2,unsigned &r3, unsigned a){
    asm volatile("ldmatrix.sync.aligned.m8n8.x4.shared.b16 {%0,%1,%2,%3}, [%4];"
        :"=r"(r0),"=r"(r1),"=r"(r2),"=r"(r3):"r"(a));
}
__device__ __forceinline__ void ldsm2t(unsigned &r0,unsigned &r1, unsigned a){
    asm volatile("ldmatrix.sync.aligned.m8n8.x2.trans.shared.b16 {%0,%1}, [%2];"
        :"=r"(r0),"=r"(r1):"r"(a));
}
__device__ __forceinline__ void ldsm4t(unsigned &r0,unsigned &r1,unsigned &r2,unsigned &r3, unsigned a){
    asm volatile("ldmatrix.sync.aligned.m8n8.x4.trans.shared.b16 {%0,%1,%2,%3}, [%4];"
        :"=r"(r0),"=r"(r1),"=r"(r2),"=r"(r3):"r"(a));
}
__device__ __forceinline__ void mmaf16(float c[4], const unsigned a[4], const unsigned b[2]){
    asm volatile("mma.sync.aligned.m16n8k16.row.col.f32.f16.f16.f32 "
        "{%0,%1,%2,%3},{%4,%5,%6,%7},{%8,%9},{%0,%1,%2,%3};"
        :"+f"(c[0]),"+f"(c[1]),"+f"(c[2]),"+f"(c[3])
        :"r"(a[0]),"r"(a[1]),"r"(a[2]),"r"(a[3]),"r"(b[0]),"r"(b[1]));
}
// pack two f32 -> half2 {lo=a, hi=b}
__device__ __forceinline__ unsigned h2pack(float a, float b){
    unsigned p;
    asm("cvt.rn.f16x2.f32 %0, %1, %2;" : "=r"(p) : "f"(b), "f"(a));
    return p;
}
// pack + exp2 both halves in one MUFU op
__device__ __forceinline__ unsigned h2ex2(float a, float b){
    unsigned p, r;
    asm("cvt.rn.f16x2.f32 %0, %1, %2;" : "=r"(p) : "f"(b), "f"(a));
    asm("ex2.approx.f16x2 %0, %1;" : "=r"(r) : "r"(p));
    return r;
}
__device__ __forceinline__ void cpa16(unsigned s, const void* g){
    asm volatile("cp.async.cg.shared.global [%0], [%1], 16;" :: "r"(s), "l"(g));
}
__device__ __forceinline__ void cpa_commit(){ asm volatile("cp.async.commit_group;"); }
template<int N> __device__ __forceinline__ void cpa_wait(){ asm volatile("cp.async.wait_group %0;" :: "n"(N)); }

// ---------------- K0b: convert big weights to fp16 ----------------
__global__ void __launch_bounds__(256) k_wconv(const float* __restrict__ wo,
                                               const float* __restrict__ w1,
                                               const float* __restrict__ w2)
{
    int i = blockIdx.x*256 + threadIdx.x;
    g_woH[i] = __float2half(wo[i]);
    g_w1H[i] = __float2half(w1[i]);
    g_w2H[i] = __float2half(w2[i]);
}

// ---------------- K1: transpose + LN1 + QKV ----------------
#define LN1_SMEM ((256*33 + 3*4096 + 64) * 4)
__global__ void __launch_bounds__(256) k_ln1_qkv(
    const float* __restrict__ x,
    const float* __restrict__ g1, const float* __restrict__ b1,
    const float* __restrict__ wq, const float* __restrict__ bq,
    const float* __restrict__ wk, const float* __restrict__ bk,
    const float* __restrict__ wv, const float* __restrict__ bv)
{
    extern __shared__ float lsm[];
    float* tile = lsm;               // [256][33]
    float* wsq  = lsm + 256*33;      // [64][64]
    float* wsk  = wsq + 4096;
    float* wsv  = wsk + 4096;
    float* mu_s = wsv + 4096;        // [32]
    float* rs_s = mu_s + 32;         // [32]

    int t  = threadIdx.x;
    int s0 = blockIdx.x*32, b = blockIdx.y;
    int tx = t & 31, ty = t >> 5;

    for (int c = ty; c < 256; c += 8)
        tile[c*33 + tx] = x[((size_t)(b*CC) + c)*SS + s0 + tx];
    for (int i = t; i < 1024; i += 256) {
        ((float4*)wsq)[i] = ((const float4*)wq)[i];
        ((float4*)wsk)[i] = ((const float4*)wk)[i];
        ((float4*)wsv)[i] = ((const float4*)wv)[i];
    }
    __syncthreads();

    #pragma unroll 4
    for (int i = 0; i < 32; i++)
        g_xt[((size_t)(b*SS) + s0 + i)*CC + t] = tile[t*33 + i];

    {
        int si = t >> 3, g = t & 7;
        float su = 0.f, sq = 0.f;
        #pragma unroll 8
        for (int c = g*32; c < g*32 + 32; c++) {
            float v = tile[c*33 + si];
            su += v; sq += v*v;
        }
        #pragma unroll
        for (int o = 1; o < 8; o <<= 1) {
            su += __shfl_xor_sync(0xffffffffu, su, o);
            sq += __shfl_xor_sync(0xffffffffu, sq, o);
        }
        if (g == 0) {
            float mu = su * (1.0f/256.0f);
            float var = sq * (1.0f/256.0f) - mu*mu;
            mu_s[si] = mu;
            rs_s[si] = rsqrtf(var + 1e-5f);
        }
    }
    __syncthreads();

    for (int c = ty; c < 256; c += 8) {
        float gg = g1[c], bb = b1[c];
        float v = tile[c*33 + tx];
        tile[c*33 + tx] = (v - mu_s[tx]) * rs_s[tx] * gg + bb;
    }
    __syncthreads();

    int h = t >> 6, dd = t & 63;
    float bqv = bq[dd], bkv = bk[dd], bvv = bv[dd];
    const float* xb = tile + (h*64)*33;
    for (int sb = 0; sb < 32; sb += 8) {
        float aq[8], ak[8], av[8];
        #pragma unroll
        for (int u = 0; u < 8; u++) { aq[u]=bqv; ak[u]=bkv; av[u]=bvv; }
        #pragma unroll 4
        for (int j = 0; j < 64; j++) {
            float wqv = wsq[j*64+dd], wkv = wsk[j*64+dd], wvv2 = wsv[j*64+dd];
            const float* xr = xb + j*33 + sb;
            #pragma unroll
            for (int u = 0; u < 8; u++) {
                float xv = xr[u];
                aq[u] = fmaf(xv, wqv, aq[u]);
                ak[u] = fmaf(xv, wkv, ak[u]);
                av[u] = fmaf(xv, wvv2, av[u]);
            }
        }
        #pragma unroll
        for (int u = 0; u < 8; u++) {
            size_t o = (((size_t)(b*HH + h))*SS + s0 + sb + u)*DD + dd;
            g_Qh[o] = __float2half(aq[u] * 0.1803368801f);  // 0.125*log2(e)
            g_Kh[o] = __float2half(ak[u]);
            g_Vh[o] = __float2half(av[u]);
        }
    }
}

// ---------------- K2: flash attention fp16, f16x2 exp, ones-column l ----------------
#define KST 72
#define KVBUF (2*64*KST)
#define ATT_SMEM ((128*KST + 3*KVBUF) * 2)
__global__ void __launch_bounds__(256) k_attn()
{
    extern __shared__ __half sm[];
    __half* Qs = sm;
    __half* KV = sm + 128*KST;

    int blk = blockIdx.x;
    int bh  = blk >> 5;
    int qt  = blk & 31;
    const __half* Qp = g_Qh + (size_t)bh * SS * DD;
    const __half* Kp = g_Kh + (size_t)bh * SS * DD;
    const __half* Vp = g_Vh + (size_t)bh * SS * DD;
    int t = threadIdx.x, w = t >> 5, lane = t & 31;

    {
        const float4* Qg = (const float4*)(Qp + (size_t)qt*128*DD);
        #pragma unroll
        for (int i = t; i < 1024; i += 256) {
            int r = i >> 3, c = i & 7;
            *(float4*)(Qs + r*KST + c*8) = Qg[i];
        }
    }

    // init V cols 64..71 of all 3 buffers: col64 = 1.0h (l-column), rest 0
    if (t < 192) {
        int bufid = t >> 6;
        int row   = t & 63;
        uint4 ones = make_uint4(0x3C00u, 0u, 0u, 0u);
        *(uint4*)(KV + bufid*KVBUF + 64*KST + row*KST + 64) = ones;
    }

    #pragma unroll
    for (int pt = 0; pt < 2; pt++) {
        __half* Kb = KV + pt*KVBUF;
        __half* Vb = Kb + 64*KST;
        const __half* Kg = Kp + (size_t)pt*64*DD;
        const __half* Vg = Vp + (size_t)pt*64*DD;
        #pragma unroll
        for (int i = t; i < 512; i += 256) {
            int r = i >> 3, c = i & 7;
            cpa16(smaddr(Kb + r*KST + c*8), Kg + r*DD + c*8);
            cpa16(smaddr(Vb + r*KST + c*8), Vg + r*DD + c*8);
        }
        cpa_commit();
    }
    __syncthreads();

    unsigned qf[4][4];
    {
        int row  = w*16 + (lane & 15);
        int colb = (lane >> 4) * 8;
        #pragma unroll
        for (int c = 0; c < 4; c++) {
            unsigned a = smaddr(Qs + row*KST + c*16 + colb);
            ldsm4(qf[c][0], qf[c][1], qf[c][2], qf[c][3], a);
        }
    }

    float o[8][4];
    #pragma unroll
    for (int j = 0; j < 8; j++) { o[j][0]=0.f;o[j][1]=0.f;o[j][2]=0.f;o[j][3]=0.f; }
    float o8[4] = {0.f, 0.f, 0.f, 0.f};   // l accumulator block (V ones column)

    int buf = 0;
    for (int kt = 0; kt < 64; kt++) {
        if (kt < 63) cpa_wait<1>(); else cpa_wait<0>();
        __syncthreads();

        if (kt + 2 < 64) {
            int nb = buf + 2; if (nb >= 3) nb -= 3;
            __half* Kb = KV + nb*KVBUF;
            __half* Vb = Kb + 64*KST;
            const __half* Kg = Kp + (size_t)(kt+2)*64*DD;
            const __half* Vg = Vp + (size_t)(kt+2)*64*DD;
            #pragma unroll
            for (int i = t; i < 512; i += 256) {
                int r = i >> 3, c = i & 7;
                cpa16(smaddr(Kb + r*KST + c*8), Kg + r*DD + c*8);
                cpa16(smaddr(Vb + r*KST + c*8), Vg + r*DD + c*8);
            }
        }
        cpa_commit();

        const __half* Ks = KV + buf*KVBUF;
        const __half* Vs = Ks + 64*KST;

        unsigned pa[4][4];
        #pragma unroll
        for (int j = 0; j < 8; j += 2) {
            float sA[4] = {0.f,0.f,0.f,0.f};
            float sB[4] = {0.f,0.f,0.f,0.f};
            #pragma unroll
            for (int c = 0; c < 4; c++) {
                unsigned kb[4];
                int krow = (j + ((lane>>4)&1))*8 + (lane&7);
                int kcol = c*16 + ((lane>>3)&1)*8;
                ldsm4(kb[0], kb[1], kb[2], kb[3], smaddr(Ks + krow*KST + kcol));
                mmaf16(sA, qf[c], kb);
                mmaf16(sB, qf[c], kb+2);
            }
            pa[j>>1][0] = h2ex2(sA[0], sA[1]);
            pa[j>>1][1] = h2ex2(sA[2], sA[3]);
            pa[j>>1][2] = h2ex2(sB[0], sB[1]);
            pa[j>>1][3] = h2ex2(sB[2], sB[3]);
        }

        #pragma unroll
        for (int c2 = 0; c2 < 4; c2++) {
            #pragma unroll
            for (int j2 = 0; j2 < 8; j2 += 2) {
                unsigned vb[4];
                int vrow = c2*16 + (lane&15);
                int vcol = (j2 + ((lane>>4)&1))*8;
                ldsm4t(vb[0], vb[1], vb[2], vb[3], smaddr(Vs + vrow*KST + vcol));
                mmaf16(o[j2],   pa[c2], vb);
                mmaf16(o[j2+1], pa[c2], vb+2);
            }
            unsigned vb2[2];
            ldsm2t(vb2[0], vb2[1], smaddr(Vs + (c2*16 + (lane&15))*KST + 64));
            mmaf16(o8, pa[c2], vb2);
        }
        buf++; if (buf >= 3) buf = 0;
    }

    float l0 = __shfl_sync(0xffffffffu, o8[0], lane & ~3);
    float l1 = __shfl_sync(0xffffffffu, o8[2], lane & ~3);

    float inv0 = 1.0f / l0, inv1 = 1.0f / l1;
    int g  = lane >> 2, qq = lane & 3;
    int b  = bh >> 2, h = bh & 3;
    int srow0 = qt*128 + w*16 + g;
    size_t base0 = ((size_t)(b*SS) + srow0)*CC + h*64;
    size_t base1 = ((size_t)(b*SS) + srow0 + 8)*CC + h*64;
    #pragma unroll
    for (int j2 = 0; j2 < 8; j2++) {
        *(unsigned*)(g_Oh2 + base0 + j2*8 + qq*2) = h2pack(o[j2][0]*inv0, o[j2][1]*inv0);
        *(unsigned*)(g_Oh2 + base1 + j2*8 + qq*2) = h2pack(o[j2][2]*inv1, o[j2][3]*inv1);
    }
}

// ---------------- fp16 GEMM: 64x256 tiles, 512 thr, 2-stage ring, 2 CTAs/SM ----------------
// MODE 0: +bias +g_xt residual -> g_av(fp32), LN2 -> g_avnh(fp16)
// MODE 1: +bias, gelu -> g_ffh(fp16)
// MODE 2: +bias +g_av residual -> out fp32 transposed [b][c][s]
#define KCH2 32
#define AHST 40          // half stride: 32+8, conflict-free ldsm4
#define BHST 264         // half stride: 256+8, conflict-free ldsm4t
#define ABUFH (64*AHST)  // halves
#define BBUFH (KCH2*BHST)
#define GEMM_SMEM01 (2*(ABUFH + BBUFH)*2)   // 44032 B
#define GEMM_SMEM2  (256*65*4)              // 66560 B (transpose epilogue)

template<int MODE>
__global__ void __launch_bounds__(512, 2) k_gemm(const __half* __restrict__ A,
                                                 const __half* __restrict__ W,
                                                 const float* __restrict__ bias,
                                                 float* __restrict__ outp,
                                                 const float* __restrict__ gamma,
                                                 const float* __restrict__ beta)
{
    extern __shared__ char smraw[];
    __half* As2 = (__half*)smraw;             // 2 x [64][AHST]
    __half* Bs2 = As2 + 2*ABUFH;              // 2 x [KCH2][BHST]
    int t = threadIdx.x, w = t >> 5, lane = t & 31;
    int wm = w >> 2, wn = w & 3;
    int r0 = blockIdx.x * 64;

    // prologue: chunks 0,1 into bufs 0,1
    #pragma unroll
    for (int pc = 0; pc < 2; pc++) {
        if (t < 256) {
            int r = t >> 2, c = t & 3;
            cpa16(smaddr(As2 + pc*ABUFH + r*AHST + c*8), A + (size_t)(r0 + r)*CC + pc*KCH2 + c*8);
        }
        #pragma unroll
        for (int u = 0; u < 2; u++) {
            int i = t + u*512;
            int k = i >> 5, c = i & 31;
            cpa16(smaddr(Bs2 + pc*BBUFH + k*BHST + c*8), W + (size_t)(pc*KCH2 + k)*CC + c*8);
        }
        cpa_commit();
    }

    float acc[8][4];
    #pragma unroll
    for (int j = 0; j < 8; j++) { acc[j][0]=0.f;acc[j][1]=0.f;acc[j][2]=0.f;acc[j][3]=0.f; }

    int buf = 0;
    for (int ch = 0; ch < 8; ch++) {
        if (ch < 7) cpa_wait<1>(); else cpa_wait<0>();
        __syncthreads();

        const __half* As = As2 + buf*ABUFH;
        const __half* Bs = Bs2 + buf*BBUFH;
        #pragma unroll
        for (int k8 = 0; k8 < KCH2; k8 += 16) {
            unsigned af[4];
            ldsm4(af[0], af[1], af[2], af[3],
                  smaddr(As + (wm*16 + (lane&15))*AHST + k8 + (lane>>4)*8));
            #pragma unroll
            for (int j = 0; j < 8; j += 2) {
                unsigned bf[4];
                int brow = k8 + (lane&15);
                int bcol = wn*64 + (j + ((lane>>4)&1))*8;
                ldsm4t(bf[0], bf[1], bf[2], bf[3], smaddr(Bs + brow*BHST + bcol));
                mmaf16(acc[j],   af, bf);
                mmaf16(acc[j+1], af, bf+2);
            }
        }

        // refill this buffer with chunk ch+2 (after all warps finished reading it)
        if (ch + 2 < 8) {
            __syncthreads();
            int kc = (ch+2)*KCH2;
            if (t < 256) {
                int r = t >> 2, c = t & 3;
                cpa16(smaddr(As2 + buf*ABUFH + r*AHST + c*8), A + (size_t)(r0 + r)*CC + kc + c*8);
            }
            #pragma unroll
            for (int u = 0; u < 2; u++) {
                int i = t + u*512;
                int k = i >> 5, c = i & 31;
                cpa16(smaddr(Bs2 + buf*BBUFH + k*BHST + c*8), W + (size_t)(kc + k)*CC + c*8);
            }
        }
        cpa_commit();
        buf ^= 1;
    }

    int ml = wm*16 + (lane>>2);
    int rlo = r0 + ml, rhi = rlo + 8;

    if (MODE == 0) {
        #pragma unroll
        for (int j = 0; j < 8; j++) {
            int c = wn*64 + j*8 + (lane&3)*2;
            float2 bz = *(const float2*)(bias + c);
            float2 x0 = *(const float2*)(g_xt + (size_t)rlo*CC + c);
            float2 x1 = *(const float2*)(g_xt + (size_t)rhi*CC + c);
            acc[j][0] += bz.x + x0.x; acc[j][1] += bz.y + x0.y;
            acc[j][2] += bz.x + x1.x; acc[j][3] += bz.y + x1.y;
            *(float2*)(g_av + (size_t)rlo*CC + c) = make_float2(acc[j][0], acc[j][1]);
            *(float2*)(g_av + (size_t)rhi*CC + c) = make_float2(acc[j][2], acc[j][3]);
        }
        float sl = 0.f, ql = 0.f, sh = 0.f, qh = 0.f;
        #pragma unroll
        for (int j = 0; j < 8; j++) {
            sl += acc[j][0] + acc[j][1];
            ql += acc[j][0]*acc[j][0] + acc[j][1]*acc[j][1];
            sh += acc[j][2] + acc[j][3];
            qh += acc[j][2]*acc[j][2] + acc[j][3]*acc[j][3];
        }
        #pragma unroll
        for (int oo = 1; oo < 4; oo <<= 1) {
            sl += __shfl_xor_sync(0xffffffffu, sl, oo);
            ql += __shfl_xor_sync(0xffffffffu, ql, oo);
            sh += __shfl_xor_sync(0xffffffffu, sh, oo);
            qh += __shfl_xor_sync(0xffffffffu, qh, oo);
        }
        __syncthreads();
        float* red = (float*)smraw;   // [4 wn][64 rows][2]
        if ((lane & 3) == 0) {
            red[(wn*64 + ml)*2 + 0] = sl;
            red[(wn*64 + ml)*2 + 1] = ql;
            red[(wn*64 + ml + 8)*2 + 0] = sh;
            red[(wn*64 + ml + 8)*2 + 1] = qh;
        }
        __syncthreads();
        float suL=0.f, qL=0.f, suH=0.f, qH=0.f;
        #pragma unroll
        for (int z = 0; z < 4; z++) {
            suL += red[(z*64+ml)*2+0];   qL += red[(z*64+ml)*2+1];
            suH += red[(z*64+ml+8)*2+0]; qH += red[(z*64+ml+8)*2+1];
        }
        float muL = suL*(1.0f/256.0f), vaL = qL*(1.0f/256.0f) - muL*muL;
        float muH = suH*(1.0f/256.0f), vaH = qH*(1.0f/256.0f) - muH*muH;
        float rsL = rsqrtf(vaL + 1e-5f), rsH = rsqrtf(vaH + 1e-5f);
        #pragma unroll
        for (int j = 0; j < 8; j++) {
            int c = wn*64 + j*8 + (lane&3)*2;
            float2 gz = *(const float2*)(gamma + c);
            float2 bz = *(const float2*)(beta + c);
            float n0 = (acc[j][0]-muL)*rsL*gz.x + bz.x;
            float n1 = (acc[j][1]-muL)*rsL*gz.y + bz.y;
            float n2 = (acc[j][2]-muH)*rsH*gz.x + bz.x;
            float n3 = (acc[j][3]-muH)*rsH*gz.y + bz.y;
            *(unsigned*)(g_avnh + (size_t)rlo*CC + c) = h2pack(n0, n1);
            *(unsigned*)(g_avnh + (size_t)rhi*CC + c) = h2pack(n2, n3);
        }
    } else if (MODE == 1) {
        #pragma unroll
        for (int j = 0; j < 8; j++) {
            int c = wn*64 + j*8 + (lane&3)*2;
            float2 bz = *(const float2*)(bias + c);
            float f0 = acc[j][0]+bz.x, f1 = acc[j][1]+bz.y;
            float f2 = acc[j][2]+bz.x, f3 = acc[j][3]+bz.y;
            float g0 = 0.5f*f0*(1.0f+erff(f0*0.70710678118654752f));
            float g1 = 0.5f*f1*(1.0f+erff(f1*0.70710678118654752f));
            float g2 = 0.5f*f2*(1.0f+erff(f2*0.70710678118654752f));
            float g3 = 0.5f*f3*(1.0f+erff(f3*0.70710678118654752f));
            *(unsigned*)(g_ffh + (size_t)rlo*CC + c) = h2pack(g0, g1);
            *(unsigned*)(g_ffh + (size_t)rhi*CC + c) = h2pack(g2, g3);
        }
    } else {
        __syncthreads();
        float* Ts = (float*)smraw;   // [256][65] = 66560 B
        #pragma unroll
        for (int j = 0; j < 8; j++) {
            int c = wn*64 + j*8 + (lane&3)*2;
            float2 bz = *(const float2*)(bias + c);
            float2 a0 = *(const float2*)(g_av + (size_t)rlo*CC + c);
            float2 a1 = *(const float2*)(g_av + (size_t)rhi*CC + c);
            Ts[(c+0)*65 + ml]     = acc[j][0]+bz.x+a0.x;
            Ts[(c+1)*65 + ml]     = acc[j][1]+bz.y+a0.y;
            Ts[(c+0)*65 + ml + 8] = acc[j][2]+bz.x+a1.x;
            Ts[(c+1)*65 + ml + 8] = acc[j][3]+bz.y+a1.y;
        }
        __syncthreads();
        int b  = r0 >> 12;
        int s0 = r0 & 4095;
        for (int i = t; i < 16384; i += 512) {
            int c = i >> 6, r = i & 63;
            outp[((size_t)(b*CC) + c)*SS + s0 + r] = Ts[c*65 + r];
        }
    }
}

extern "C" void kernel_launch(void* const* d_in, const int* in_sizes, int n_in,
                              void* d_out, int out_size)
{
    const float* x     = (const float*)d_in[0];
    const float* ln1_g = (const float*)d_in[1];
    const float* ln1_b = (const float*)d_in[2];
    const float* wq    = (const float*)d_in[3];
    const float* bq    = (const float*)d_in[4];
    const float* wk    = (const float*)d_in[5];
    const float* bk    = (const float*)d_in[6];
    const float* wv    = (const float*)d_in[7];
    const float* bv    = (const float*)d_in[8];
    const float* wo    = (const float*)d_in[9];
    const float* bo    = (const float*)d_in[10];
    const float* ln2_g = (const float*)d_in[11];
    const float* ln2_b = (const float*)d_in[12];
    const float* w1    = (const float*)d_in[13];
    const float* b1    = (const float*)d_in[14];
    const float* w2    = (const float*)d_in[15];
    const float* b2    = (const float*)d_in[16];
    float* out = (float*)d_out;

    cudaFuncSetAttribute(k_ln1_qkv, cudaFuncAttributeMaxDynamicSharedMemorySize, LN1_SMEM);
    cudaFuncSetAttribute(k_attn,    cudaFuncAttributeMaxDynamicSharedMemorySize, ATT_SMEM);
    cudaFuncSetAttribute(k_gemm<0>, cudaFuncAttributeMaxDynamicSharedMemorySize, GEMM_SMEM01);
    cudaFuncSetAttribute(k_gemm<1>, cudaFuncAttributeMaxDynamicSharedMemorySize, GEMM_SMEM01);
    cudaFuncSetAttribute(k_gemm<2>, cudaFuncAttributeMaxDynamicSharedMemorySize, GEMM_SMEM2);

    __half* woH; cudaGetSymbolAddress((void**)&woH, g_woH);
    __half* w1H; cudaGetSymbolAddress((void**)&w1H, g_w1H);
    __half* w2H; cudaGetSymbolAddress((void**)&w2H, g_w2H);
    __half* Oh;  cudaGetSymbolAddress((void**)&Oh,  g_Oh2);
    __half* avn; cudaGetSymbolAddress((void**)&avn, g_avnh);
    __half* ff;  cudaGetSymbolAddress((void**)&ff,  g_ffh);

    k_wconv<<<256, 256>>>(wo, w1, w2);
    k_ln1_qkv<<<dim3(SS/32, BB), 256, LN1_SMEM>>>(x, ln1_g, ln1_b, wq, bq, wk, bk, wv, bv);
    k_attn<<<BB*HH*(SS/128), 256, ATT_SMEM>>>();
    k_gemm<0><<<NROW/64, 512, GEMM_SMEM01>>>(Oh,  woH, bo, nullptr, ln2_g, ln2_b);
    k_gemm<1><<<NROW/64, 512, GEMM_SMEM01>>>(avn, w1H, b1, nullptr, nullptr, nullptr);
    k_gemm<2><<<NROW/64, 512, GEMM_SMEM2>>>(ff,  w2H, b2, out,     nullptr, nullptr);
}